// round 1
// baseline (speedup 1.0000x reference)
#include <cuda_runtime.h>
#include <cstdint>

#define Bb 2
#define Nn 2048
#define Ff 128
#define FEe 8
#define Hh 4
#define Cc 64
#define HC 256
#define TI 16
#define TJ 64
#define TB 128
#define PROW 68   // padded P row stride in words (17 float4s -> 16B aligned, low conflicts)

// scratch (device globals: allocation-free)
__device__ float g_h [Bb*Nn*HC];   // [B,N,H*C]  4 MB, L2-resident
__device__ float g_ss[Bb*Nn*Hh];   // s_src
__device__ float g_sd[Bb*Nn*Hh];   // s_dst

// ---------------- Kernel A: h = X @ W_gat ; s_src/s_dst ----------------
__global__ __launch_bounds__(256) void precompute_kernel(
    const float* __restrict__ X, const float* __restrict__ Wg,
    const float* __restrict__ asrc, const float* __restrict__ adst)
{
    __shared__ float xs[16][Ff];     // 16 node rows of X
    __shared__ float wsm[32][HC];    // W chunk: [f-sub][h*64+c]
    __shared__ float red_s[8][16];
    __shared__ float red_d[8][16];

    const int t   = threadIdx.x;          // 0..255 == channel h*64+c
    const int bn0 = blockIdx.x * 16;      // 16 nodes per block

    for (int k = t; k < 16*Ff; k += 256)
        xs[k >> 7][k & 127] = X[(size_t)bn0*Ff + k];

    const int h = t >> 6, c = t & 63;
    float acc[16];
#pragma unroll
    for (int g = 0; g < 16; ++g) acc[g] = 0.f;

    for (int fc = 0; fc < Ff; fc += 32) {
        __syncthreads();
#pragma unroll
        for (int lf = 0; lf < 32; ++lf)
            wsm[lf][t] = Wg[h*(Ff*Cc) + (fc+lf)*Cc + c];
        __syncthreads();
#pragma unroll
        for (int lf = 0; lf < 32; ++lf) {
            const float wv = wsm[lf][t];
#pragma unroll
            for (int g = 0; g < 16; ++g)
                acc[g] = fmaf(xs[g][fc+lf], wv, acc[g]);
        }
    }

    const float as = asrc[t], ad = adst[t];
#pragma unroll
    for (int g = 0; g < 16; ++g)
        g_h[(size_t)(bn0+g)*HC + t] = acc[g];

    const int w = t >> 5;   // warp id; head h owns warps 2h, 2h+1
#pragma unroll
    for (int g = 0; g < 16; ++g) {
        float ps = acc[g]*as, pd = acc[g]*ad;
#pragma unroll
        for (int o = 16; o; o >>= 1) {
            ps += __shfl_down_sync(0xffffffffu, ps, o);
            pd += __shfl_down_sync(0xffffffffu, pd, o);
        }
        if ((t & 31) == 0) { red_s[w][g] = ps; red_d[w][g] = pd; }
    }
    __syncthreads();
    if (t < 64) {
        const int g = t & 15, hh = t >> 4;
        g_ss[(size_t)(bn0+g)*Hh + hh] = red_s[2*hh][g] + red_s[2*hh+1][g];
        g_sd[(size_t)(bn0+g)*Hh + hh] = red_d[2*hh][g] + red_d[2*hh+1][g];
    }
}

// ---------------- Kernel B: fused gate + softmax + AV + ELU + LayerNorm ----------------
__global__ __launch_bounds__(TB) void gat_kernel(
    const float* __restrict__ A,  const float* __restrict__ E,
    const float* __restrict__ W_edge, const float* __restrict__ b_edge,
    const float* __restrict__ b_gat,  const float* __restrict__ gamma,
    const float* __restrict__ beta,   float* __restrict__ out)
{
    extern __shared__ float sm[];
    float* hv  = sm;                       // [TJ][HC]        16384 f
    float* Pm  = hv + TJ*HC;               // [TJ][PROW]       4352 f
    float* sdj = Pm + TJ*PROW;             // [TJ][H]           256 f

    const int t     = threadIdx.x;         // 0..127
    const int bi0   = blockIdx.x * TI;     // global node-row base (bn space)
    const int b     = bi0 / Nn;
    const int i_loc = t >> 3;              // 0..15
    const int g8    = t & 7;               // 8 threads per i-row
    const int bn_i  = bi0 + i_loc;

    float we[FEe];
#pragma unroll
    for (int e = 0; e < FEe; ++e) we[e] = W_edge[e];
    const float be = b_edge[0];

    float ss[Hh];
#pragma unroll
    for (int h = 0; h < Hh; ++h) ss[h] = g_ss[(size_t)bn_i*Hh + h];

    const float* Arow = A + (size_t)bn_i * Nn;
    const float* Erow = E + (size_t)bn_i * Nn * FEe;

    float acc[32];
#pragma unroll
    for (int q = 0; q < 32; ++q) acc[q] = 0.f;
    float lsum[Hh] = {0.f, 0.f, 0.f, 0.f};

    for (int j0 = 0; j0 < Nn; j0 += TJ) {
        __syncthreads();  // previous AV done before overwriting hv/Pm
        // load hv tile [TJ][HC] (coalesced float4)
        {
            const float4* src = (const float4*)(g_h + ((size_t)b*Nn + j0)*HC);
            float4* dst = (float4*)hv;
#pragma unroll
            for (int k = 0; k < (TJ*HC/4)/TB; ++k)   // 32 iters
                dst[t + k*TB] = src[t + k*TB];
        }
        sdj[t]      = g_sd[((size_t)b*Nn + j0)*Hh + t];
        sdj[t + TB] = g_sd[((size_t)b*Nn + j0)*Hh + t + TB];
        __syncthreads();

        // ---- P phase: 8 (i,j) pairs per thread: j = j0 + g8 + 8k ----
#pragma unroll
        for (int k = 0; k < 8; ++k) {
            const int jj = g8 + k*8;
            const int j  = j0 + jj;
            const float4* ep = (const float4*)(Erow + (size_t)j * FEe);
            const float4 e0 = __ldcs(ep);
            const float4 e1 = __ldcs(ep + 1);
            float x = be;
            x = fmaf(e0.x, we[0], x); x = fmaf(e0.y, we[1], x);
            x = fmaf(e0.z, we[2], x); x = fmaf(e0.w, we[3], x);
            x = fmaf(e1.x, we[4], x); x = fmaf(e1.y, we[5], x);
            x = fmaf(e1.z, we[6], x); x = fmaf(e1.w, we[7], x);
            const float gate = __fdividef(1.f, 1.f + __expf(-x));
            const float a = __ldcs(Arow + j) * gate;
            const bool z = (a == 0.f);

            float4 pv;
            float l0 = ss[0] + sdj[jj*Hh+0]; l0 = l0 >= 0.f ? l0 : 0.2f*l0;
            float l1 = ss[1] + sdj[jj*Hh+1]; l1 = l1 >= 0.f ? l1 : 0.2f*l1;
            float l2 = ss[2] + sdj[jj*Hh+2]; l2 = l2 >= 0.f ? l2 : 0.2f*l2;
            float l3 = ss[3] + sdj[jj*Hh+3]; l3 = l3 >= 0.f ? l3 : 0.2f*l3;
            pv.x = z ? 0.f : __expf(l0);
            pv.y = z ? 0.f : __expf(l1);
            pv.z = z ? 0.f : __expf(l2);
            pv.w = z ? 0.f : __expf(l3);
            lsum[0] += pv.x; lsum[1] += pv.y; lsum[2] += pv.z; lsum[3] += pv.w;
            *(float4*)(Pm + jj*PROW + i_loc*4) = pv;
        }
        __syncthreads();

        // ---- AV phase: thread owns channels ch = k*32 + g8*4 (+0..3), head = k>>1 ----
#pragma unroll 2
        for (int jj = 0; jj < TJ; ++jj) {
            const float4 p4 = *(const float4*)(Pm + jj*PROW + i_loc*4);
            const float ph[4] = {p4.x, p4.y, p4.z, p4.w};
            const float* hrow = hv + jj*HC + g8*4;
#pragma unroll
            for (int k = 0; k < 8; ++k) {
                const float4 vv = *(const float4*)(hrow + k*32);
                const float p = ph[k >> 1];
                acc[k*4+0] = fmaf(p, vv.x, acc[k*4+0]);
                acc[k*4+1] = fmaf(p, vv.y, acc[k*4+1]);
                acc[k*4+2] = fmaf(p, vv.z, acc[k*4+2]);
                acc[k*4+3] = fmaf(p, vv.w, acc[k*4+3]);
            }
        }
    }

    // reduce lsum across the 8 threads of this i-row (aligned 8-lane groups)
#pragma unroll
    for (int h = 0; h < Hh; ++h) {
        lsum[h] += __shfl_xor_sync(0xffffffffu, lsum[h], 4);
        lsum[h] += __shfl_xor_sync(0xffffffffu, lsum[h], 2);
        lsum[h] += __shfl_xor_sync(0xffffffffu, lsum[h], 1);
    }
    float inv[Hh];
#pragma unroll
    for (int h = 0; h < Hh; ++h) inv[h] = __fdividef(1.f, lsum[h]);

    // normalize + bias + ELU, partial LN sums
    float v[32];
    float s1 = 0.f, s2 = 0.f;
#pragma unroll
    for (int k = 0; k < 8; ++k) {
        const int ch = k*32 + g8*4;
        const float4 bg = *(const float4*)(b_gat + ch);
        const float iv = inv[k >> 1];
        float xv[4] = { fmaf(acc[k*4+0], iv, bg.x), fmaf(acc[k*4+1], iv, bg.y),
                        fmaf(acc[k*4+2], iv, bg.z), fmaf(acc[k*4+3], iv, bg.w) };
#pragma unroll
        for (int u = 0; u < 4; ++u) {
            float x = xv[u];
            x = x > 0.f ? x : expm1f(x);
            v[k*4+u] = x;
            s1 += x;
            s2 = fmaf(x, x, s2);
        }
    }
    s1 += __shfl_xor_sync(0xffffffffu, s1, 4);
    s1 += __shfl_xor_sync(0xffffffffu, s1, 2);
    s1 += __shfl_xor_sync(0xffffffffu, s1, 1);
    s2 += __shfl_xor_sync(0xffffffffu, s2, 4);
    s2 += __shfl_xor_sync(0xffffffffu, s2, 2);
    s2 += __shfl_xor_sync(0xffffffffu, s2, 1);

    const float mu   = s1 * (1.f/HC);
    const float var  = fmaf(-mu, mu, s2 * (1.f/HC));
    const float rstd = rsqrtf(var + 1e-3f);

#pragma unroll
    for (int k = 0; k < 8; ++k) {
        const int ch = k*32 + g8*4;
        const float4 ga  = *(const float4*)(gamma + ch);
        const float4 be4 = *(const float4*)(beta  + ch);
        float4 o;
        o.x = fmaf((v[k*4+0]-mu)*rstd, ga.x, be4.x);
        o.y = fmaf((v[k*4+1]-mu)*rstd, ga.y, be4.y);
        o.z = fmaf((v[k*4+2]-mu)*rstd, ga.z, be4.z);
        o.w = fmaf((v[k*4+3]-mu)*rstd, ga.w, be4.w);
        *(float4*)(out + (size_t)bn_i*HC + ch) = o;
    }
}

extern "C" void kernel_launch(void* const* d_in, const int* in_sizes, int n_in,
                              void* d_out, int out_size)
{
    (void)in_sizes; (void)n_in; (void)out_size;
    const float* X      = (const float*)d_in[0];
    const float* A      = (const float*)d_in[1];
    const float* E      = (const float*)d_in[2];
    const float* W_edge = (const float*)d_in[3];
    const float* b_edge = (const float*)d_in[4];
    const float* W_gat  = (const float*)d_in[5];
    const float* a_src  = (const float*)d_in[6];
    const float* a_dst  = (const float*)d_in[7];
    const float* b_gat  = (const float*)d_in[8];
    const float* gamma  = (const float*)d_in[9];
    const float* beta   = (const float*)d_in[10];
    float* out = (float*)d_out;

    const int smemB = (TJ*HC + TJ*PROW + TJ*Hh) * (int)sizeof(float);  // 83968 B
    cudaFuncSetAttribute(gat_kernel, cudaFuncAttributeMaxDynamicSharedMemorySize, smemB);

    precompute_kernel<<<(Bb*Nn)/16, 256>>>(X, W_gat, a_src, a_dst);
    gat_kernel<<<(Bb*Nn)/TI, TB, smemB>>>(A, E, W_edge, b_edge, b_gat, gamma, beta, out);
}

// round 2
// speedup vs baseline: 2.7716x; 2.7716x over previous
#include <cuda_runtime.h>
#include <cstdint>

#define Bb 2
#define Nn 2048
#define Ff 128
#define Hh 4
#define Cc 64
#define HC 256
#define TI 16
#define TJ 64
#define TB 256
#define PROW 68   // Pm row stride: 4 heads * 16 i + 4 pad

// scratch (device globals: allocation-free)
__device__ float g_h [Bb*Nn*HC];   // [B,N,H*C]  4 MB
__device__ float g_ss[Bb*Nn*Hh];   // s_src
__device__ float g_sd[Bb*Nn*Hh];   // s_dst

typedef unsigned long long u64;

__device__ __forceinline__ u64 fma2(u64 a, u64 b, u64 c) {
    u64 d;
    asm("fma.rn.f32x2 %0, %1, %2, %3;" : "=l"(d) : "l"(a), "l"(b), "l"(c));
    return d;
}
__device__ __forceinline__ u64 pack2(float x) {
    u64 d;
    asm("mov.b64 %0, {%1, %1};" : "=l"(d) : "r"(__float_as_uint(x)));
    return d;
}
__device__ __forceinline__ void unpack2(u64 v, float& lo, float& hi) {
    unsigned a, b;
    asm("mov.b64 {%0, %1}, %2;" : "=r"(a), "=r"(b) : "l"(v));
    lo = __uint_as_float(a); hi = __uint_as_float(b);
}

// ---------------- Kernel A: h = X @ W_gat ; s_src/s_dst ----------------
__global__ __launch_bounds__(256) void precompute_kernel(
    const float* __restrict__ X, const float* __restrict__ Wg,
    const float* __restrict__ asrc, const float* __restrict__ adst)
{
    __shared__ float xs[16][Ff];
    __shared__ float wsm[32][HC];
    __shared__ float red_s[8][16];
    __shared__ float red_d[8][16];

    const int t   = threadIdx.x;          // 0..255 == channel h*64+c
    const int bn0 = blockIdx.x * 16;

    for (int k = t; k < 16*Ff; k += 256)
        xs[k >> 7][k & 127] = X[(size_t)bn0*Ff + k];

    const int h = t >> 6, c = t & 63;
    float acc[16];
#pragma unroll
    for (int g = 0; g < 16; ++g) acc[g] = 0.f;

    for (int fc = 0; fc < Ff; fc += 32) {
        __syncthreads();
#pragma unroll
        for (int lf = 0; lf < 32; ++lf)
            wsm[lf][t] = Wg[h*(Ff*Cc) + (fc+lf)*Cc + c];
        __syncthreads();
#pragma unroll
        for (int lf = 0; lf < 32; ++lf) {
            const float wv = wsm[lf][t];
#pragma unroll
            for (int g = 0; g < 16; ++g)
                acc[g] = fmaf(xs[g][fc+lf], wv, acc[g]);
        }
    }

    const float as = asrc[t], ad = adst[t];
#pragma unroll
    for (int g = 0; g < 16; ++g)
        g_h[(size_t)(bn0+g)*HC + t] = acc[g];

    const int w = t >> 5;
#pragma unroll
    for (int g = 0; g < 16; ++g) {
        float ps = acc[g]*as, pd = acc[g]*ad;
#pragma unroll
        for (int o = 16; o; o >>= 1) {
            ps += __shfl_down_sync(0xffffffffu, ps, o);
            pd += __shfl_down_sync(0xffffffffu, pd, o);
        }
        if ((t & 31) == 0) { red_s[w][g] = ps; red_d[w][g] = pd; }
    }
    __syncthreads();
    if (t < 64) {
        const int g = t & 15, hh = t >> 4;
        g_ss[(size_t)(bn0+g)*Hh + hh] = red_s[2*hh][g] + red_s[2*hh+1][g];
        g_sd[(size_t)(bn0+g)*Hh + hh] = red_d[2*hh][g] + red_d[2*hh+1][g];
    }
}

// ---------------- Kernel B: fused mask + softmax + AV + ELU + LayerNorm ----------------
__global__ __launch_bounds__(TB) void gat_kernel(
    const float* __restrict__ A,
    const float* __restrict__ b_gat, const float* __restrict__ gamma,
    const float* __restrict__ beta,  float* __restrict__ out)
{
    extern __shared__ float sm[];
    float* hv   = sm;                      // [TJ][HC]       16384 f
    float* Pm   = hv + TJ*HC;              // [TJ][PROW]      4352 f
    float* sdj  = Pm + TJ*PROW;            // [TJ][4]          256 f
    float* invs = sdj + TJ*Hh;             // [16][4]           64 f
    float* redp = invs + 64;               // [8 warps][4 i][2] 64 f

    const int t   = threadIdx.x;           // 0..255
    const int bi0 = blockIdx.x * TI;
    const int b   = bi0 / Nn;

    // P-phase roles: fixed i-row, 16 j-lanes
    const int iP  = t >> 4;                // 0..15
    const int jl  = t & 15;
    const int bnP = bi0 + iP;

    // AV-phase roles: 4-channel group, 4-i quad
    const int g    = t & 63;               // channels 4g..4g+3
    const int q    = t >> 6;               // i = 4q..4q+3
    const int head = g >> 4;

    float ssP[Hh];
#pragma unroll
    for (int h = 0; h < Hh; ++h) ssP[h] = g_ss[(size_t)bnP*Hh + h];
    const float* ArowP = A + (size_t)bnP * Nn;

    u64 acc2[4][2];
#pragma unroll
    for (int ii = 0; ii < 4; ++ii) { acc2[ii][0] = 0ull; acc2[ii][1] = 0ull; }
    float lsum[Hh] = {0.f, 0.f, 0.f, 0.f};

    for (int j0 = 0; j0 < Nn; j0 += TJ) {
        __syncthreads();
        // stage hv tile [TJ][HC]
        {
            const float4* src = (const float4*)(g_h + ((size_t)b*Nn + j0)*HC);
            float4* dst = (float4*)hv;
#pragma unroll
            for (int k = 0; k < 16; ++k)
                dst[t + k*TB] = src[t + k*TB];
        }
        sdj[t] = g_sd[((size_t)b*Nn + j0)*Hh + t];
        __syncthreads();

        // ---- P phase: mask + leaky + exp ----
#pragma unroll
        for (int k = 0; k < 4; ++k) {
            const int jj = jl + 16*k;
            const float a = __ldcs(ArowP + j0 + jj);
            const bool z = (a == 0.f);
#pragma unroll
            for (int h = 0; h < Hh; ++h) {
                float l = ssP[h] + sdj[jj*Hh + h];
                l = l >= 0.f ? l : 0.2f*l;
                const float p = z ? 0.f : __expf(l);
                lsum[h] += p;
                Pm[jj*PROW + h*16 + iP] = p;
            }
        }
        __syncthreads();

        // ---- AV phase: outer-product register tile, packed f32x2 FMA ----
        const float* hvg = hv + 4*g;
        const float* pmg = Pm + head*16 + 4*q;
#pragma unroll 4
        for (int jj = 0; jj < TJ; ++jj) {
            const ulonglong2 h2 = *(const ulonglong2*)(hvg + jj*HC);
            const float4 p4 = *(const float4*)(pmg + jj*PROW);
            const u64 p0 = pack2(p4.x), p1 = pack2(p4.y);
            const u64 p2 = pack2(p4.z), p3 = pack2(p4.w);
            acc2[0][0] = fma2(p0, h2.x, acc2[0][0]);
            acc2[0][1] = fma2(p0, h2.y, acc2[0][1]);
            acc2[1][0] = fma2(p1, h2.x, acc2[1][0]);
            acc2[1][1] = fma2(p1, h2.y, acc2[1][1]);
            acc2[2][0] = fma2(p2, h2.x, acc2[2][0]);
            acc2[2][1] = fma2(p2, h2.y, acc2[2][1]);
            acc2[3][0] = fma2(p3, h2.x, acc2[3][0]);
            acc2[3][1] = fma2(p3, h2.y, acc2[3][1]);
        }
    }

    // ---- softmax denominators: reduce lsum across the 16 j-lanes of row iP ----
#pragma unroll
    for (int h = 0; h < Hh; ++h) {
#pragma unroll
        for (int o = 8; o; o >>= 1)
            lsum[h] += __shfl_xor_sync(0xffffffffu, lsum[h], o);
    }
    if (jl == 0) {
#pragma unroll
        for (int h = 0; h < Hh; ++h)
            invs[iP*Hh + h] = __fdividef(1.f, lsum[h]);
    }
    __syncthreads();

    // ---- normalize + bias + ELU, LN partial sums ----
    const float4 bg  = *(const float4*)(b_gat + 4*g);
    const float4 ga  = *(const float4*)(gamma + 4*g);
    const float4 bt  = *(const float4*)(beta  + 4*g);

    float vout[4][4], s1[4], s2[4];
#pragma unroll
    for (int ii = 0; ii < 4; ++ii) {
        const int i = 4*q + ii;
        const float iv = invs[i*Hh + head];
        float a0, a1, a2, a3;
        unpack2(acc2[ii][0], a0, a1);
        unpack2(acc2[ii][1], a2, a3);
        float x0 = fmaf(a0, iv, bg.x);
        float x1 = fmaf(a1, iv, bg.y);
        float x2 = fmaf(a2, iv, bg.z);
        float x3 = fmaf(a3, iv, bg.w);
        x0 = x0 > 0.f ? x0 : expm1f(x0);
        x1 = x1 > 0.f ? x1 : expm1f(x1);
        x2 = x2 > 0.f ? x2 : expm1f(x2);
        x3 = x3 > 0.f ? x3 : expm1f(x3);
        vout[ii][0] = x0; vout[ii][1] = x1; vout[ii][2] = x2; vout[ii][3] = x3;
        s1[ii] = x0 + x1 + x2 + x3;
        s2[ii] = fmaf(x0,x0, fmaf(x1,x1, fmaf(x2,x2, x3*x3)));
    }

    // warp-level LN reduction (all 32 lanes of a warp share q)
#pragma unroll
    for (int ii = 0; ii < 4; ++ii) {
#pragma unroll
        for (int o = 16; o; o >>= 1) {
            s1[ii] += __shfl_xor_sync(0xffffffffu, s1[ii], o);
            s2[ii] += __shfl_xor_sync(0xffffffffu, s2[ii], o);
        }
    }
    const int w = t >> 5;
    if ((t & 31) == 0) {
#pragma unroll
        for (int ii = 0; ii < 4; ++ii) {
            redp[(w*4 + ii)*2 + 0] = s1[ii];
            redp[(w*4 + ii)*2 + 1] = s2[ii];
        }
    }
    __syncthreads();

#pragma unroll
    for (int ii = 0; ii < 4; ++ii) {
        const float S1 = redp[((2*q)*4 + ii)*2 + 0] + redp[((2*q+1)*4 + ii)*2 + 0];
        const float S2 = redp[((2*q)*4 + ii)*2 + 1] + redp[((2*q+1)*4 + ii)*2 + 1];
        const float mu   = S1 * (1.f/HC);
        const float var  = fmaf(-mu, mu, S2 * (1.f/HC));
        const float rstd = rsqrtf(var + 1e-3f);
        float4 o;
        o.x = fmaf((vout[ii][0]-mu)*rstd, ga.x, bt.x);
        o.y = fmaf((vout[ii][1]-mu)*rstd, ga.y, bt.y);
        o.z = fmaf((vout[ii][2]-mu)*rstd, ga.z, bt.z);
        o.w = fmaf((vout[ii][3]-mu)*rstd, ga.w, bt.w);
        *(float4*)(out + (size_t)(bi0 + 4*q + ii)*HC + 4*g) = o;
    }
}

extern "C" void kernel_launch(void* const* d_in, const int* in_sizes, int n_in,
                              void* d_out, int out_size)
{
    (void)in_sizes; (void)n_in; (void)out_size;
    const float* X      = (const float*)d_in[0];
    const float* A      = (const float*)d_in[1];
    // d_in[2]=E, d_in[3]=W_edge, d_in[4]=b_edge: dead — gate only affects the
    // A==0 mask and sigmoid>0 always, A*gate==0 <=> A==0.
    const float* W_gat  = (const float*)d_in[5];
    const float* a_src  = (const float*)d_in[6];
    const float* a_dst  = (const float*)d_in[7];
    const float* b_gat  = (const float*)d_in[8];
    const float* gamma  = (const float*)d_in[9];
    const float* beta   = (const float*)d_in[10];
    float* out = (float*)d_out;

    const int smemB = (TJ*HC + TJ*PROW + TJ*Hh + 64 + 64) * (int)sizeof(float);
    cudaFuncSetAttribute(gat_kernel, cudaFuncAttributeMaxDynamicSharedMemorySize, smemB);

    precompute_kernel<<<(Bb*Nn)/16, 256>>>(X, W_gat, a_src, a_dst);
    gat_kernel<<<(Bb*Nn)/TI, TB, smemB>>>(A, b_gat, gamma, beta, out);
}

// round 4
// speedup vs baseline: 5.7856x; 2.0875x over previous
#include <cuda_runtime.h>
#include <cstdint>

#define Bb 2
#define Nn 2048
#define Ff 128
#define Hh 4
#define HC 256
#define MI 128
#define SPLIT 4
#define JR (Nn/SPLIT)            // 512 j per CTA
#define NT (JR/64)               // 8 j-tiles
#define NCTA ((Bb*Nn/MI)*SPLIT)  // 128

// smem layout for kernel B (bytes)
#define SMB_AF 65536
#define SMB_SD 73728
#define SMB_TOT 74752

// device scratch (allocation-free)
__device__ float g_hT2[Bb*(Nn/64)*16384];   // [b][T][h][s][c][q][half], tf32-rounded (4 MB)
__device__ float g_ss [Bb*Nn*Hh];
__device__ float g_sd [Bb*Nn*Hh];
__device__ float g_part[(size_t)NCTA*MI*HC]; // 16.8 MB partial numerators
__device__ float g_lsum[NCTA*MI*Hh];

__device__ __forceinline__ unsigned tf32u(float x) {
    unsigned u; asm("cvt.rna.tf32.f32 %0, %1;" : "=r"(u) : "f"(x)); return u;
}
__device__ __forceinline__ void mma_tf32(float& d0, float& d1, float& d2, float& d3,
                                         unsigned a0, unsigned a1, unsigned a2, unsigned a3,
                                         unsigned b0, unsigned b1) {
    asm volatile("mma.sync.aligned.m16n8k8.row.col.f32.tf32.tf32.f32 "
                 "{%0,%1,%2,%3}, {%4,%5,%6,%7}, {%8,%9}, {%0,%1,%2,%3};"
                 : "+f"(d0), "+f"(d1), "+f"(d2), "+f"(d3)
                 : "r"(a0), "r"(a1), "r"(a2), "r"(a3), "r"(b0), "r"(b1));
}

// ---------------- Kernel A: h = X @ W_gat -> g_hT2 (tf32 pair layout) ; s_src/s_dst ----------------
__global__ __launch_bounds__(256) void precompute_kernel(
    const float* __restrict__ X, const float* __restrict__ Wg,
    const float* __restrict__ asrc, const float* __restrict__ adst)
{
    __shared__ float xs[16][Ff];
    __shared__ float wsm[32][HC];       // reused as tr[16][258] after GEMM
    __shared__ float red_s[8][16];
    __shared__ float red_d[8][16];

    const int t   = threadIdx.x;        // channel ch = h*64+c
    const int bn0 = blockIdx.x * 16;

    for (int k = t; k < 16*Ff; k += 256)
        xs[k >> 7][k & 127] = X[(size_t)bn0*Ff + k];

    const int hh0 = t >> 6, c0 = t & 63;
    float acc[16];
#pragma unroll
    for (int g = 0; g < 16; ++g) acc[g] = 0.f;

    for (int fc = 0; fc < Ff; fc += 32) {
        __syncthreads();
#pragma unroll
        for (int lf = 0; lf < 32; ++lf)
            wsm[lf][t] = Wg[hh0*(Ff*64) + (fc+lf)*64 + c0];
        __syncthreads();
#pragma unroll
        for (int lf = 0; lf < 32; ++lf) {
            const float wv = wsm[lf][t];
#pragma unroll
            for (int g = 0; g < 16; ++g)
                acc[g] = fmaf(xs[g][fc+lf], wv, acc[g]);
        }
    }

    // s_src / s_dst (full fp32 precision)
    const float as = asrc[t], ad = adst[t];
    const int w = t >> 5;
#pragma unroll
    for (int g = 0; g < 16; ++g) {
        float ps = acc[g]*as, pd = acc[g]*ad;
#pragma unroll
        for (int o = 16; o; o >>= 1) {
            ps += __shfl_down_sync(0xffffffffu, ps, o);
            pd += __shfl_down_sync(0xffffffffu, pd, o);
        }
        if ((t & 31) == 0) { red_s[w][g] = ps; red_d[w][g] = pd; }
    }
    __syncthreads();
    if (t < 64) {
        const int g = t & 15, hx = t >> 4;
        g_ss[(size_t)(bn0+g)*Hh + hx] = red_s[2*hx][g] + red_s[2*hx+1][g];
        g_sd[(size_t)(bn0+g)*Hh + hx] = red_d[2*hx][g] + red_d[2*hx+1][g];
    }

    // transpose tf32-rounded acc through smem (overlay wsm) -> g_hT2 pair layout
    float* tr = &wsm[0][0];             // stride 258
#pragma unroll
    for (int g = 0; g < 16; ++g)
        tr[g*258 + t] = __uint_as_float(tf32u(acc[g]));
    __syncthreads();

    const int b   = bn0 >> 11;
    const int nl  = bn0 & (Nn-1);
    const int T   = nl >> 6;
    const int s0  = (nl & 63) >> 3;
    float* dst = g_hT2 + ((size_t)(b*32 + T))*16384;
#pragma unroll
    for (int rep = 0; rep < 2; ++rep) {
        const int u = t + rep*256;      // 0..511
        const int ch = u & 255, s_rel = u >> 8;
        float v[8];
#pragma unroll
        for (int k = 0; k < 8; ++k) {
            const int qq = k >> 1, hf = k & 1;
            v[k] = tr[(8*s_rel + qq + 4*hf)*258 + ch];
        }
        const int s = s0 + s_rel;
        const int hx = ch >> 6, c = ch & 63;
        float* p = dst + (((hx*8 + s)*64 + c) << 3);
        *(float4*)p       = make_float4(v[0], v[1], v[2], v[3]);
        *(float4*)(p + 4) = make_float4(v[4], v[5], v[6], v[7]);
    }
}

// ---------------- Kernel B: fragment-native P + mma.sync tf32 ----------------
__global__ __launch_bounds__(256, 1) void gat_mma_kernel(const float* __restrict__ A)
{
    extern __shared__ char sm[];
    float2* sB  = (float2*)sm;                 // [h][s][c][q] pairs (65536 B)
    char*   sAf = sm + SMB_AF;                 // flags [s][i][q][pair] (8192 B)
    float2* sSD = (float2*)(sm + SMB_SD);      // [h][s][q] pairs (1024 B)

    const int t    = threadIdx.x;
    const int w    = t >> 5, lane = t & 31;
    const int h    = w & 3;                    // head
    const int hf   = w >> 2;                   // i-half (0/1)
    const int rL   = lane >> 2, q = lane & 3;

    const int cta   = blockIdx.x;
    const int split = cta & 3, ib = cta >> 2;
    const int b     = ib >> 4;
    const int i0    = (ib & 15) * MI;
    const int jbase = split * JR;

    float ssh[4][2];
#pragma unroll
    for (int g = 0; g < 4; ++g)
#pragma unroll
        for (int rh = 0; rh < 2; ++rh)
            ssh[g][rh] = g_ss[((size_t)b*Nn + i0 + hf*64 + 16*g + rL + 8*rh)*Hh + h];

    float acc[4][8][4];
#pragma unroll
    for (int g = 0; g < 4; ++g)
#pragma unroll
        for (int n = 0; n < 8; ++n)
#pragma unroll
            for (int u = 0; u < 4; ++u) acc[g][n][u] = 0.f;
    float lacc[4][2] = {{0.f,0.f},{0.f,0.f},{0.f,0.f},{0.f,0.f}};

    for (int tt = 0; tt < NT; ++tt) {
        const int j0 = jbase + tt*64;
        __syncthreads();

        // stage B: straight copy (already pair-layout + tf32)
        {
            const float4* src = (const float4*)(g_hT2 + ((size_t)(b*32 + split*8 + tt))*16384);
            float4* dstv = (float4*)sB;
#pragma unroll
            for (int k = 0; k < 16; ++k)
                dstv[t + k*256] = src[t + k*256];
        }
        // stage adjacency flags (1 byte per edge)
#pragma unroll
        for (int k = 0; k < 4; ++k) {
            const int o = t + k*256;           // 0..1023
            const int i = o >> 3, s = o & 7;
            const float4* ap = (const float4*)(A + ((size_t)b*Nn + i0 + i)*Nn + j0 + 8*s);
            const float4 f0 = __ldcs(ap);
            const float4 f1 = __ldcs(ap + 1);
            unsigned long long m = 0;
            m |= (unsigned long long)(f0.x != 0.f) << 0;
            m |= (unsigned long long)(f1.x != 0.f) << 8;
            m |= (unsigned long long)(f0.y != 0.f) << 16;
            m |= (unsigned long long)(f1.y != 0.f) << 24;
            m |= (unsigned long long)(f0.z != 0.f) << 32;
            m |= (unsigned long long)(f1.z != 0.f) << 40;
            m |= (unsigned long long)(f0.w != 0.f) << 48;
            m |= (unsigned long long)(f1.w != 0.f) << 56;
            *(unsigned long long*)(sAf + (s*128 + i)*8) = m;
        }
        // stage sdj pairs
        if (t < 128) {
            const int h2 = t >> 5, e = t & 31, s = e >> 2, q2 = e & 3;
            const float a0 = g_sd[((size_t)b*Nn + j0 + 8*s + q2)*Hh + h2];
            const float a1 = g_sd[((size_t)b*Nn + j0 + 8*s + q2 + 4)*Hh + h2];
            sSD[(h2*8 + s)*4 + q2] = make_float2(a0, a1);
        }
        __syncthreads();

        // main: per k-step, fragment-native P + mma
#pragma unroll
        for (int s = 0; s < 8; ++s) {
            float2 bf[8];
            const float2* bp = sB + ((h*8 + s)*64 + rL)*4 + q;
#pragma unroll
            for (int n = 0; n < 8; ++n) bf[n] = bp[n*32];
            const float2 sd2 = sSD[(h*8 + s)*4 + q];

#pragma unroll
            for (int g = 0; g < 4; ++g) {
                const int iA = hf*64 + 16*g + rL;
                const unsigned fl0 = *(const unsigned short*)(sAf + (s*128 + iA)*8 + q*2);
                const unsigned fl1 = *(const unsigned short*)(sAf + (s*128 + iA + 8)*8 + q*2);
                float l00 = ssh[g][0] + sd2.x;
                float l01 = ssh[g][0] + sd2.y;
                float l10 = ssh[g][1] + sd2.x;
                float l11 = ssh[g][1] + sd2.y;
                l00 = fmaxf(l00, 0.2f*l00);
                l01 = fmaxf(l01, 0.2f*l01);
                l10 = fmaxf(l10, 0.2f*l10);
                l11 = fmaxf(l11, 0.2f*l11);
                const float p00 = (fl0 & 0xffu) ? __expf(l00) : 0.f;
                const float p01 = (fl0 >> 8)    ? __expf(l01) : 0.f;
                const float p10 = (fl1 & 0xffu) ? __expf(l10) : 0.f;
                const float p11 = (fl1 >> 8)    ? __expf(l11) : 0.f;
                const unsigned a0 = tf32u(p00);   // (row,   k)
                const unsigned a1 = tf32u(p10);   // (row+8, k)
                const unsigned a2 = tf32u(p01);   // (row,   k+4)
                const unsigned a3 = tf32u(p11);   // (row+8, k+4)
                lacc[g][0] += __uint_as_float(a0) + __uint_as_float(a2);
                lacc[g][1] += __uint_as_float(a1) + __uint_as_float(a3);
#pragma unroll
                for (int n = 0; n < 8; ++n)
                    mma_tf32(acc[g][n][0], acc[g][n][1], acc[g][n][2], acc[g][n][3],
                             a0, a1, a2, a3,
                             __float_as_uint(bf[n].x), __float_as_uint(bf[n].y));
            }
        }
    }

    // lsum: reduce over the 4 q-lanes of each quad
#pragma unroll
    for (int g = 0; g < 4; ++g)
#pragma unroll
        for (int rh = 0; rh < 2; ++rh) {
            float v = lacc[g][rh];
            v += __shfl_xor_sync(0xffffffffu, v, 1);
            v += __shfl_xor_sync(0xffffffffu, v, 2);
            if (q == 0)
                g_lsum[((size_t)cta*MI + hf*64 + 16*g + rL + 8*rh)*Hh + h] = v;
        }

    // store partial numerators
    float* gp = g_part + (size_t)cta*MI*HC;
#pragma unroll
    for (int g = 0; g < 4; ++g) {
        const int i  = hf*64 + 16*g + rL;
#pragma unroll
        for (int n = 0; n < 8; ++n) {
            const int ch = h*64 + 8*n + 2*q;
            *(float2*)(gp + (size_t)i*HC + ch)       = make_float2(acc[g][n][0], acc[g][n][1]);
            *(float2*)(gp + (size_t)(i+8)*HC + ch)   = make_float2(acc[g][n][2], acc[g][n][3]);
        }
    }
}

// ---------------- Kernel C: merge splits + normalize + bias + ELU + LayerNorm ----------------
__global__ __launch_bounds__(256) void merge_kernel(
    const float* __restrict__ bgat, const float* __restrict__ gamma,
    const float* __restrict__ beta, float* __restrict__ out)
{
    const int t = threadIdx.x, w = t >> 5, lane = t & 31;
    const int row = blockIdx.x*8 + w;      // 0..4095
    const int ib = row >> 7, il = row & 127;
    const int hd = lane >> 3;

    float4 n0 = {0,0,0,0}, n1 = {0,0,0,0};
    float ls = 0.f;
#pragma unroll
    for (int s = 0; s < SPLIT; ++s) {
        const int cta = ib*SPLIT + s;
        const float4* p = (const float4*)(g_part + ((size_t)cta*MI + il)*HC + lane*8);
        const float4 x = p[0], y = p[1];
        n0.x += x.x; n0.y += x.y; n0.z += x.z; n0.w += x.w;
        n1.x += y.x; n1.y += y.y; n1.z += y.z; n1.w += y.w;
        ls += g_lsum[((size_t)cta*MI + il)*Hh + hd];
    }
    const float inv = __fdividef(1.f, ls);

    const int ch = lane*8;
    const float4 bgA = *(const float4*)(bgat + ch), bgB = *(const float4*)(bgat + ch + 4);

    float v[8];
    v[0] = fmaf(n0.x, inv, bgA.x); v[1] = fmaf(n0.y, inv, bgA.y);
    v[2] = fmaf(n0.z, inv, bgA.z); v[3] = fmaf(n0.w, inv, bgA.w);
    v[4] = fmaf(n1.x, inv, bgB.x); v[5] = fmaf(n1.y, inv, bgB.y);
    v[6] = fmaf(n1.z, inv, bgB.z); v[7] = fmaf(n1.w, inv, bgB.w);

    float s1 = 0.f, s2 = 0.f;
#pragma unroll
    for (int k = 0; k < 8; ++k) {
        float x = v[k];
        x = x > 0.f ? x : expm1f(x);
        v[k] = x;
        s1 += x;
        s2 = fmaf(x, x, s2);
    }
#pragma unroll
    for (int o = 16; o; o >>= 1) {
        s1 += __shfl_xor_sync(0xffffffffu, s1, o);
        s2 += __shfl_xor_sync(0xffffffffu, s2, o);
    }
    const float mu   = s1 * (1.f/HC);
    const float var  = fmaf(-mu, mu, s2 * (1.f/HC));
    const float rstd = rsqrtf(var + 1e-3f);

    const float4 gaA = *(const float4*)(gamma + ch), gaB = *(const float4*)(gamma + ch + 4);
    const float4 btA = *(const float4*)(beta  + ch), btB = *(const float4*)(beta  + ch + 4);
    float4 o1, o2;
    o1.x = fmaf((v[0]-mu)*rstd, gaA.x, btA.x); o1.y = fmaf((v[1]-mu)*rstd, gaA.y, btA.y);
    o1.z = fmaf((v[2]-mu)*rstd, gaA.z, btA.z); o1.w = fmaf((v[3]-mu)*rstd, gaA.w, btA.w);
    o2.x = fmaf((v[4]-mu)*rstd, gaB.x, btB.x); o2.y = fmaf((v[5]-mu)*rstd, gaB.y, btB.y);
    o2.z = fmaf((v[6]-mu)*rstd, gaB.z, btB.z); o2.w = fmaf((v[7]-mu)*rstd, gaB.w, btB.w);
    *(float4*)(out + (size_t)row*HC + ch)     = o1;
    *(float4*)(out + (size_t)row*HC + ch + 4) = o2;
}

extern "C" void kernel_launch(void* const* d_in, const int* in_sizes, int n_in,
                              void* d_out, int out_size)
{
    (void)in_sizes; (void)n_in; (void)out_size;
    const float* X      = (const float*)d_in[0];
    const float* A      = (const float*)d_in[1];
    // d_in[2..4] (E, W_edge, b_edge) are dead: sigmoid>0 always => A*gate==0 <=> A==0.
    const float* W_gat  = (const float*)d_in[5];
    const float* a_src  = (const float*)d_in[6];
    const float* a_dst  = (const float*)d_in[7];
    const float* b_gat  = (const float*)d_in[8];
    const float* gamma  = (const float*)d_in[9];
    const float* beta   = (const float*)d_in[10];
    float* out = (float*)d_out;

    cudaFuncSetAttribute(gat_mma_kernel, cudaFuncAttributeMaxDynamicSharedMemorySize, SMB_TOT);

    precompute_kernel<<<(Bb*Nn)/16, 256>>>(X, W_gat, a_src, a_dst);
    gat_mma_kernel<<<NCTA, 256, SMB_TOT>>>(A);
    merge_kernel<<<(Bb*Nn)/8, 256>>>(b_gat, gamma, beta, out);
}

// round 5
// speedup vs baseline: 6.4546x; 1.1156x over previous
#include <cuda_runtime.h>
#include <cstdint>

#define Bb 2
#define Nn 2048
#define Ff 128
#define Hh 4
#define HC 256
#define MI 128
#define SPLIT 4
#define JR (Nn/SPLIT)            // 512 j per CTA
#define NT (JR/64)               // 8 j-tiles
#define NCTA ((Bb*Nn/MI)*SPLIT)  // 128

// kernel-B dynamic smem layout (bytes): double-buffered
#define SMB_B(st)  ((st)*65536)                  // h-tile: 16384 floats/stage
#define SMB_A(st)  (131072 + (st)*34816)         // A-tile: [128][68] floats/stage
#define SMB_S(st)  (200704 + (st)*1024)          // sd-tile: [64][4] floats/stage
#define SMB_TOT    202752

// device scratch (allocation-free)
__device__ float g_hT2[Bb*(Nn/64)*16384];   // [b][T][h][s][c][q][half], tf32-rounded (4 MB)
__device__ float g_ss [Bb*Nn*Hh];
__device__ float g_sd [Bb*Nn*Hh];
__device__ float g_part[(size_t)NCTA*MI*HC]; // 16.8 MB partial numerators
__device__ float g_lsum[NCTA*MI*Hh];

__device__ __forceinline__ unsigned tf32u(float x) {
    unsigned u; asm("cvt.rna.tf32.f32 %0, %1;" : "=r"(u) : "f"(x)); return u;
}
__device__ __forceinline__ void mma_tf32(float& d0, float& d1, float& d2, float& d3,
                                         unsigned a0, unsigned a1, unsigned a2, unsigned a3,
                                         unsigned b0, unsigned b1) {
    asm volatile("mma.sync.aligned.m16n8k8.row.col.f32.tf32.tf32.f32 "
                 "{%0,%1,%2,%3}, {%4,%5,%6,%7}, {%8,%9}, {%0,%1,%2,%3};"
                 : "+f"(d0), "+f"(d1), "+f"(d2), "+f"(d3)
                 : "r"(a0), "r"(a1), "r"(a2), "r"(a3), "r"(b0), "r"(b1));
}
__device__ __forceinline__ uint32_t smem_u32(const void* p) {
    uint32_t a;
    asm("{ .reg .u64 t; cvta.to.shared.u64 t, %1; cvt.u32.u64 %0, t; }" : "=r"(a) : "l"(p));
    return a;
}
__device__ __forceinline__ void cp16(uint32_t dst, const void* src) {
    asm volatile("cp.async.cg.shared.global [%0], [%1], 16;" :: "r"(dst), "l"(src));
}
#define CP_COMMIT() asm volatile("cp.async.commit_group;" ::: "memory")
#define CP_WAIT(n)  asm volatile("cp.async.wait_group %0;" :: "n"(n) : "memory")

// ---------------- Kernel A: h = X @ W_gat -> g_hT2 (tf32 pair layout) ; s_src/s_dst ----------------
__global__ __launch_bounds__(256) void precompute_kernel(
    const float* __restrict__ X, const float* __restrict__ Wg,
    const float* __restrict__ asrc, const float* __restrict__ adst)
{
    __shared__ float xs[16][Ff];        // 8 KB
    __shared__ float ws[32][HC];        // 32 KB; overlaid by tr[16][260] after GEMM
    __shared__ float red_s[16][4];
    __shared__ float red_d[16][4];

    const int t   = threadIdx.x;
    const int bn0 = blockIdx.x * 16;
    const int c4  = t & 63;             // channel quad: channels 4c4..4c4+3
    const int nq  = t >> 6;             // node quad:    nodes    4nq..4nq+3

    // stage X [16][128] (coalesced float4)
#pragma unroll
    for (int r = 0; r < 2; ++r) {
        const int u = t + r*256;        // 0..511 float4s
        const int n = u >> 5, f4 = u & 31;
        *(float4*)&xs[n][f4*4] = *(const float4*)(X + (size_t)(bn0+n)*Ff + f4*4);
    }

    float acc[4][4];
#pragma unroll
    for (int jj = 0; jj < 4; ++jj)
#pragma unroll
        for (int cc = 0; cc < 4; ++cc) acc[jj][cc] = 0.f;

    const int hh = t >> 6, cc0 = t & 63;
    for (int fc = 0; fc < Ff; fc += 32) {
        __syncthreads();
#pragma unroll
        for (int lf = 0; lf < 32; ++lf)
            ws[lf][t] = Wg[hh*(Ff*64) + (fc+lf)*64 + cc0];
        __syncthreads();
#pragma unroll
        for (int lf = 0; lf < 32; ++lf) {
            const float4 w4 = *(const float4*)&ws[lf][4*c4];   // 1 LDS.128
            const float x0 = xs[4*nq+0][fc+lf];                // broadcast LDS
            const float x1 = xs[4*nq+1][fc+lf];
            const float x2 = xs[4*nq+2][fc+lf];
            const float x3 = xs[4*nq+3][fc+lf];
            acc[0][0] = fmaf(x0, w4.x, acc[0][0]); acc[0][1] = fmaf(x0, w4.y, acc[0][1]);
            acc[0][2] = fmaf(x0, w4.z, acc[0][2]); acc[0][3] = fmaf(x0, w4.w, acc[0][3]);
            acc[1][0] = fmaf(x1, w4.x, acc[1][0]); acc[1][1] = fmaf(x1, w4.y, acc[1][1]);
            acc[1][2] = fmaf(x1, w4.z, acc[1][2]); acc[1][3] = fmaf(x1, w4.w, acc[1][3]);
            acc[2][0] = fmaf(x2, w4.x, acc[2][0]); acc[2][1] = fmaf(x2, w4.y, acc[2][1]);
            acc[2][2] = fmaf(x2, w4.z, acc[2][2]); acc[2][3] = fmaf(x2, w4.w, acc[2][3]);
            acc[3][0] = fmaf(x3, w4.x, acc[3][0]); acc[3][1] = fmaf(x3, w4.y, acc[3][1]);
            acc[3][2] = fmaf(x3, w4.z, acc[3][2]); acc[3][3] = fmaf(x3, w4.w, acc[3][3]);
        }
    }

    // s_src/s_dst partials over this thread's 4 channels, reduce over the 16
    // c4-lanes of the same head (16-lane aligned groups)
    const float4 as4 = *(const float4*)(asrc + 4*c4);
    const float4 ad4 = *(const float4*)(adst + 4*c4);
#pragma unroll
    for (int jj = 0; jj < 4; ++jj) {
        float ps = acc[jj][0]*as4.x + acc[jj][1]*as4.y + acc[jj][2]*as4.z + acc[jj][3]*as4.w;
        float pd = acc[jj][0]*ad4.x + acc[jj][1]*ad4.y + acc[jj][2]*ad4.z + acc[jj][3]*ad4.w;
#pragma unroll
        for (int o = 1; o < 16; o <<= 1) {
            ps += __shfl_xor_sync(0xffffffffu, ps, o);
            pd += __shfl_xor_sync(0xffffffffu, pd, o);
        }
        if ((t & 15) == 0) {
            const int head = c4 >> 4;
            red_s[4*nq+jj][head] = ps;
            red_d[4*nq+jj][head] = pd;
        }
    }
    __syncthreads();   // ws reads done; red_s/red_d visible

    // tr overlay on ws: [16 nodes][260], tf32-rounded
    float* tr = &ws[0][0];
#pragma unroll
    for (int jj = 0; jj < 4; ++jj) {
        float4 v;
        v.x = __uint_as_float(tf32u(acc[jj][0]));
        v.y = __uint_as_float(tf32u(acc[jj][1]));
        v.z = __uint_as_float(tf32u(acc[jj][2]));
        v.w = __uint_as_float(tf32u(acc[jj][3]));
        *(float4*)&tr[(4*nq+jj)*260 + 4*c4] = v;
    }
    if (t < 64) {
        const int n = t >> 2, h = t & 3;
        g_ss[(size_t)(bn0+n)*Hh + h] = red_s[n][h];
        g_sd[(size_t)(bn0+n)*Hh + h] = red_d[n][h];
    }
    __syncthreads();

    // store pair-layout tiles to g_hT2
    const int b  = bn0 >> 11;
    const int nl = bn0 & (Nn-1);
    const int T  = nl >> 6;
    const int s0 = (nl & 63) >> 3;
    float* dst = g_hT2 + ((size_t)(b*32 + T))*16384;
#pragma unroll
    for (int rep = 0; rep < 2; ++rep) {
        const int u = t + rep*256;      // 0..511
        const int ch = u & 255, s_rel = u >> 8;
        float v[8];
#pragma unroll
        for (int k = 0; k < 8; ++k) {
            const int qq = k >> 1, hf = k & 1;
            v[k] = tr[(8*s_rel + qq + 4*hf)*260 + ch];
        }
        const int s = s0 + s_rel;
        const int hx = ch >> 6, c = ch & 63;
        float* p = dst + (((hx*8 + s)*64 + c) << 3);
        *(float4*)p       = make_float4(v[0], v[1], v[2], v[3]);
        *(float4*)(p + 4) = make_float4(v[4], v[5], v[6], v[7]);
    }
}

// ---------------- Kernel B: pipelined fragment-native P + mma.sync tf32 ----------------
__global__ __launch_bounds__(256, 1) void gat_mma_kernel(const float* __restrict__ A)
{
    extern __shared__ char sm[];
    const uint32_t smb = smem_u32(sm);

    const int t    = threadIdx.x;
    const int w    = t >> 5, lane = t & 31;
    const int h    = w & 3;                    // head
    const int hf   = w >> 2;                   // i-half (0/1)
    const int rL   = lane >> 2, q = lane & 3;

    const int cta   = blockIdx.x;
    const int split = cta & 3, ib = cta >> 2;
    const int b     = ib >> 4;
    const int i0    = (ib & 15) * MI;
    const int jbase = split * JR;

    float ssh[4][2];
#pragma unroll
    for (int g = 0; g < 4; ++g)
#pragma unroll
        for (int rh = 0; rh < 2; ++rh)
            ssh[g][rh] = g_ss[((size_t)b*Nn + i0 + hf*64 + 16*g + rL + 8*rh)*Hh + h];

    float acc[4][8][4];
#pragma unroll
    for (int g = 0; g < 4; ++g)
#pragma unroll
        for (int n = 0; n < 8; ++n)
#pragma unroll
            for (int u = 0; u < 4; ++u) acc[g][n][u] = 0.f;
    float lacc[4][2] = {{0.f,0.f},{0.f,0.f},{0.f,0.f},{0.f,0.f}};

    // ---- async stage of tile tt into buffer st ----
    auto stage = [&](int tt, int st) {
        const int j0 = jbase + tt*64;
        const char* srcB = (const char*)(g_hT2 + (size_t)(b*32 + split*8 + tt)*16384);
#pragma unroll
        for (int k = 0; k < 16; ++k) {
            const int u = t + k*256;
            cp16(smb + SMB_B(st) + u*16, srcB + u*16);
        }
#pragma unroll
        for (int k = 0; k < 8; ++k) {
            const int u = t + k*256;               // 0..2047
            const int i = u >> 4, jj = u & 15;
            cp16(smb + SMB_A(st) + i*272 + jj*16,
                 (const char*)(A + ((size_t)b*Nn + i0 + i)*Nn + j0) + jj*16);
        }
        if (t < 64)
            cp16(smb + SMB_S(st) + t*16,
                 (const char*)(g_sd + ((size_t)b*Nn + j0)*Hh) + t*16);
        CP_COMMIT();
    };

    stage(0, 0);

    for (int tt = 0; tt < NT; ++tt) {
        const int st = tt & 1;
        if (tt + 1 < NT) { stage(tt + 1, st ^ 1); CP_WAIT(1); }
        else             { CP_WAIT(0); }
        __syncthreads();

        const float2* sB  = (const float2*)(sm + SMB_B(st));
        const float*  sAf = (const float*)(sm + SMB_A(st));
        const float*  sSD = (const float*)(sm + SMB_S(st));

#pragma unroll
        for (int s = 0; s < 8; ++s) {
            float2 bf[8];
            const float2* bp = sB + ((h*8 + s)*64 + rL)*4 + q;
#pragma unroll
            for (int n = 0; n < 8; ++n) bf[n] = bp[n*32];
            const float sdx = sSD[(8*s + q)*4 + h];
            const float sdy = sSD[(8*s + q + 4)*4 + h];

#pragma unroll
            for (int g = 0; g < 4; ++g) {
                const int iA = hf*64 + 16*g + rL;
                const float a00 = sAf[iA*68 + 8*s + q];
                const float a01 = sAf[iA*68 + 8*s + q + 4];
                const float a10 = sAf[(iA+8)*68 + 8*s + q];
                const float a11 = sAf[(iA+8)*68 + 8*s + q + 4];
                float l00 = ssh[g][0] + sdx;
                float l01 = ssh[g][0] + sdy;
                float l10 = ssh[g][1] + sdx;
                float l11 = ssh[g][1] + sdy;
                l00 = fmaxf(l00, 0.2f*l00);
                l01 = fmaxf(l01, 0.2f*l01);
                l10 = fmaxf(l10, 0.2f*l10);
                l11 = fmaxf(l11, 0.2f*l11);
                const float p00 = (a00 != 0.f) ? __expf(l00) : 0.f;
                const float p01 = (a01 != 0.f) ? __expf(l01) : 0.f;
                const float p10 = (a10 != 0.f) ? __expf(l10) : 0.f;
                const float p11 = (a11 != 0.f) ? __expf(l11) : 0.f;
                const unsigned f0 = tf32u(p00);   // (row,   k)
                const unsigned f1 = tf32u(p10);   // (row+8, k)
                const unsigned f2 = tf32u(p01);   // (row,   k+4)
                const unsigned f3 = tf32u(p11);   // (row+8, k+4)
                lacc[g][0] += __uint_as_float(f0) + __uint_as_float(f2);
                lacc[g][1] += __uint_as_float(f1) + __uint_as_float(f3);
#pragma unroll
                for (int n = 0; n < 8; ++n)
                    mma_tf32(acc[g][n][0], acc[g][n][1], acc[g][n][2], acc[g][n][3],
                             f0, f1, f2, f3,
                             __float_as_uint(bf[n].x), __float_as_uint(bf[n].y));
            }
        }
        __syncthreads();   // done reading st before it is re-staged next iter
    }

    // lsum: reduce over the 4 q-lanes of each quad
#pragma unroll
    for (int g = 0; g < 4; ++g)
#pragma unroll
        for (int rh = 0; rh < 2; ++rh) {
            float v = lacc[g][rh];
            v += __shfl_xor_sync(0xffffffffu, v, 1);
            v += __shfl_xor_sync(0xffffffffu, v, 2);
            if (q == 0)
                g_lsum[((size_t)cta*MI + hf*64 + 16*g + rL + 8*rh)*Hh + h] = v;
        }

    // store partial numerators
    float* gp = g_part + (size_t)cta*MI*HC;
#pragma unroll
    for (int g = 0; g < 4; ++g) {
        const int i = hf*64 + 16*g + rL;
#pragma unroll
        for (int n = 0; n < 8; ++n) {
            const int ch = h*64 + 8*n + 2*q;
            *(float2*)(gp + (size_t)i*HC + ch)     = make_float2(acc[g][n][0], acc[g][n][1]);
            *(float2*)(gp + (size_t)(i+8)*HC + ch) = make_float2(acc[g][n][2], acc[g][n][3]);
        }
    }
}

// ---------------- Kernel C: merge splits + normalize + bias + ELU + LayerNorm ----------------
__global__ __launch_bounds__(256) void merge_kernel(
    const float* __restrict__ bgat, const float* __restrict__ gamma,
    const float* __restrict__ beta, float* __restrict__ out)
{
    const int t = threadIdx.x, w = t >> 5, lane = t & 31;
    const int row = blockIdx.x*8 + w;      // 0..4095
    const int ib = row >> 7, il = row & 127;
    const int hd = lane >> 3;

    float4 n0 = {0,0,0,0}, n1 = {0,0,0,0};
    float ls = 0.f;
#pragma unroll
    for (int s = 0; s < SPLIT; ++s) {
        const int cta = ib*SPLIT + s;
        const float4* p = (const float4*)(g_part + ((size_t)cta*MI + il)*HC + lane*8);
        const float4 x = p[0], y = p[1];
        n0.x += x.x; n0.y += x.y; n0.z += x.z; n0.w += x.w;
        n1.x += y.x; n1.y += y.y; n1.z += y.z; n1.w += y.w;
        ls += g_lsum[((size_t)cta*MI + il)*Hh + hd];
    }
    const float inv = __fdividef(1.f, ls);

    const int ch = lane*8;
    const float4 bgA = *(const float4*)(bgat + ch), bgB = *(const float4*)(bgat + ch + 4);

    float v[8];
    v[0] = fmaf(n0.x, inv, bgA.x); v[1] = fmaf(n0.y, inv, bgA.y);
    v[2] = fmaf(n0.z, inv, bgA.z); v[3] = fmaf(n0.w, inv, bgA.w);
    v[4] = fmaf(n1.x, inv, bgB.x); v[5] = fmaf(n1.y, inv, bgB.y);
    v[6] = fmaf(n1.z, inv, bgB.z); v[7] = fmaf(n1.w, inv, bgB.w);

    float s1 = 0.f, s2 = 0.f;
#pragma unroll
    for (int k = 0; k < 8; ++k) {
        float x = v[k];
        x = x > 0.f ? x : expm1f(x);
        v[k] = x;
        s1 += x;
        s2 = fmaf(x, x, s2);
    }
#pragma unroll
    for (int o = 16; o; o >>= 1) {
        s1 += __shfl_xor_sync(0xffffffffu, s1, o);
        s2 += __shfl_xor_sync(0xffffffffu, s2, o);
    }
    const float mu   = s1 * (1.f/HC);
    const float var  = fmaf(-mu, mu, s2 * (1.f/HC));
    const float rstd = rsqrtf(var + 1e-3f);

    const float4 gaA = *(const float4*)(gamma + ch), gaB = *(const float4*)(gamma + ch + 4);
    const float4 btA = *(const float4*)(beta  + ch), btB = *(const float4*)(beta  + ch + 4);
    float4 o1, o2;
    o1.x = fmaf((v[0]-mu)*rstd, gaA.x, btA.x); o1.y = fmaf((v[1]-mu)*rstd, gaA.y, btA.y);
    o1.z = fmaf((v[2]-mu)*rstd, gaA.z, btA.z); o1.w = fmaf((v[3]-mu)*rstd, gaA.w, btA.w);
    o2.x = fmaf((v[4]-mu)*rstd, gaB.x, btB.x); o2.y = fmaf((v[5]-mu)*rstd, gaB.y, btB.y);
    o2.z = fmaf((v[6]-mu)*rstd, gaB.z, btB.z); o2.w = fmaf((v[7]-mu)*rstd, gaB.w, btB.w);
    *(float4*)(out + (size_t)row*HC + ch)     = o1;
    *(float4*)(out + (size_t)row*HC + ch + 4) = o2;
}

extern "C" void kernel_launch(void* const* d_in, const int* in_sizes, int n_in,
                              void* d_out, int out_size)
{
    (void)in_sizes; (void)n_in; (void)out_size;
    const float* X      = (const float*)d_in[0];
    const float* A      = (const float*)d_in[1];
    // d_in[2..4] (E, W_edge, b_edge) are dead: sigmoid>0 always => A*gate==0 <=> A==0.
    const float* W_gat  = (const float*)d_in[5];
    const float* a_src  = (const float*)d_in[6];
    const float* a_dst  = (const float*)d_in[7];
    const float* b_gat  = (const float*)d_in[8];
    const float* gamma  = (const float*)d_in[9];
    const float* beta   = (const float*)d_in[10];
    float* out = (float*)d_out;

    cudaFuncSetAttribute(gat_mma_kernel, cudaFuncAttributeMaxDynamicSharedMemorySize, SMB_TOT);

    precompute_kernel<<<(Bb*Nn)/16, 256>>>(X, W_gat, a_src, a_dst);
    gat_mma_kernel<<<NCTA, 256, SMB_TOT>>>(A);
    merge_kernel<<<(Bb*Nn)/8, 256>>>(b_gat, gamma, beta, out);
}

// round 6
// speedup vs baseline: 8.1664x; 1.2652x over previous
#include <cuda_runtime.h>
#include <cstdint>

#define Bb 2
#define Nn 2048
#define Ff 128
#define Hh 4
#define HC 256
#define MI 128
#define SPLIT 4
#define JR (Nn/SPLIT)            // 512 j per CTA
#define NT (JR/64)               // 8 j-tiles
#define NCTA ((Bb*Nn/MI)*SPLIT)  // 128

// kernel-B dynamic smem layout (bytes): double-buffered
#define SMB_B(st)  ((st)*65536)                  // h-tile: 16384 floats/stage
#define SMB_A(st)  (131072 + (st)*34816)         // A-tile: [128][68] floats/stage
#define SMB_S(st)  (200704 + (st)*1024)          // sd-tile: [64][4] floats/stage
#define SMB_TOT    202752

// precompute dynamic smem layout (bytes)
#define SMP_XS     0                             // [32][128] floats = 16384
#define SMP_WS(st) (16384 + (st)*32768)          // [32][256] floats per stage
#define SMP_RS     81920                         // [32][4]
#define SMP_RD     82432
#define SMP_TOT    82944
// tr overlay lives on the ws double buffer after the GEMM
#define SMP_TR     16384

// device scratch (allocation-free)
__device__ float g_hT2[Bb*(Nn/64)*16384];   // [b][T][h][s][c][q][half], tf32-rounded (4 MB)
__device__ float g_ss [Bb*Nn*Hh];
__device__ float g_sd [Bb*Nn*Hh];
__device__ float g_part[(size_t)NCTA*MI*HC]; // 16.8 MB partial numerators
__device__ float g_lsum[NCTA*MI*Hh];

__device__ __forceinline__ unsigned tf32u(float x) {
    unsigned u; asm("cvt.rna.tf32.f32 %0, %1;" : "=r"(u) : "f"(x)); return u;
}
__device__ __forceinline__ void mma_tf32(float& d0, float& d1, float& d2, float& d3,
                                         unsigned a0, unsigned a1, unsigned a2, unsigned a3,
                                         unsigned b0, unsigned b1) {
    asm volatile("mma.sync.aligned.m16n8k8.row.col.f32.tf32.tf32.f32 "
                 "{%0,%1,%2,%3}, {%4,%5,%6,%7}, {%8,%9}, {%0,%1,%2,%3};"
                 : "+f"(d0), "+f"(d1), "+f"(d2), "+f"(d3)
                 : "r"(a0), "r"(a1), "r"(a2), "r"(a3), "r"(b0), "r"(b1));
}
__device__ __forceinline__ uint32_t smem_u32(const void* p) {
    uint32_t a;
    asm("{ .reg .u64 t; cvta.to.shared.u64 t, %1; cvt.u32.u64 %0, t; }" : "=r"(a) : "l"(p));
    return a;
}
__device__ __forceinline__ void cp16(uint32_t dst, const void* src) {
    asm volatile("cp.async.cg.shared.global [%0], [%1], 16;" :: "r"(dst), "l"(src));
}
#define CP_COMMIT() asm volatile("cp.async.commit_group;" ::: "memory")
#define CP_WAIT(n)  asm volatile("cp.async.wait_group %0;" :: "n"(n) : "memory")

// ---------------- Kernel A: h = X @ W_gat -> g_hT2 (tf32 pair layout) ; s_src/s_dst ----------------
__global__ __launch_bounds__(512) void precompute_kernel(
    const float* __restrict__ X, const float* __restrict__ Wg,
    const float* __restrict__ asrc, const float* __restrict__ adst)
{
    extern __shared__ char smp[];
    float* xs    = (float*)(smp + SMP_XS);      // [32][128]
    float* red_s = (float*)(smp + SMP_RS);      // [32][4]
    float* red_d = (float*)(smp + SMP_RD);

    const int t   = threadIdx.x;                // 0..511
    const int bn0 = blockIdx.x * 32;
    const int c4  = t & 63;                     // channel quad
    const int nq  = t >> 6;                     // node quad (0..7)
    const uint32_t smb = smem_u32(smp);

    // stage X [32][128] (coalesced float4)
#pragma unroll
    for (int r = 0; r < 2; ++r) {
        const int u = t + r*512;                // 0..1023 float4s
        const int n = u >> 5, f4 = u & 31;
        *(float4*)&xs[n*Ff + f4*4] = *(const float4*)(X + (size_t)(bn0+n)*Ff + f4*4);
    }

    // async stage of W chunk (32 f-rows) into buffer st
    auto stageW = [&](int fc, int st) {
#pragma unroll
        for (int k = 0; k < 4; ++k) {
            const int u = t + k*512;            // 0..2047 float4s
            const int lf = u >> 6, cq = u & 63;
            const int hh = cq >> 4, cl = cq & 15;
            cp16(smb + SMP_WS(st) + (lf*256 + cq*4)*4,
                 Wg + (size_t)hh*(Ff*64) + (size_t)(fc+lf)*64 + cl*4);
        }
        CP_COMMIT();
    };

    float acc[4][4];
#pragma unroll
    for (int jj = 0; jj < 4; ++jj)
#pragma unroll
        for (int cc = 0; cc < 4; ++cc) acc[jj][cc] = 0.f;

    stageW(0, 0);
    for (int ch = 0; ch < 4; ++ch) {
        const int st = ch & 1;
        if (ch + 1 < 4) { stageW(32*(ch+1), st ^ 1); CP_WAIT(1); }
        else            { CP_WAIT(0); }
        __syncthreads();
        const float* ws = (const float*)(smp + SMP_WS(st));
#pragma unroll
        for (int lf = 0; lf < 32; ++lf) {
            const float4 w4 = *(const float4*)&ws[lf*256 + 4*c4];   // 1 LDS.128
            const float x0 = xs[(4*nq+0)*Ff + 32*ch + lf];          // broadcast
            const float x1 = xs[(4*nq+1)*Ff + 32*ch + lf];
            const float x2 = xs[(4*nq+2)*Ff + 32*ch + lf];
            const float x3 = xs[(4*nq+3)*Ff + 32*ch + lf];
            acc[0][0] = fmaf(x0, w4.x, acc[0][0]); acc[0][1] = fmaf(x0, w4.y, acc[0][1]);
            acc[0][2] = fmaf(x0, w4.z, acc[0][2]); acc[0][3] = fmaf(x0, w4.w, acc[0][3]);
            acc[1][0] = fmaf(x1, w4.x, acc[1][0]); acc[1][1] = fmaf(x1, w4.y, acc[1][1]);
            acc[1][2] = fmaf(x1, w4.z, acc[1][2]); acc[1][3] = fmaf(x1, w4.w, acc[1][3]);
            acc[2][0] = fmaf(x2, w4.x, acc[2][0]); acc[2][1] = fmaf(x2, w4.y, acc[2][1]);
            acc[2][2] = fmaf(x2, w4.z, acc[2][2]); acc[2][3] = fmaf(x2, w4.w, acc[2][3]);
            acc[3][0] = fmaf(x3, w4.x, acc[3][0]); acc[3][1] = fmaf(x3, w4.y, acc[3][1]);
            acc[3][2] = fmaf(x3, w4.z, acc[3][2]); acc[3][3] = fmaf(x3, w4.w, acc[3][3]);
        }
        __syncthreads();
    }

    // s_src/s_dst partials over this thread's 4 channels; reduce over the 16
    // c4-lanes of the same head (aligned 16-lane groups)
    const float4 as4 = *(const float4*)(asrc + 4*c4);
    const float4 ad4 = *(const float4*)(adst + 4*c4);
#pragma unroll
    for (int jj = 0; jj < 4; ++jj) {
        float ps = acc[jj][0]*as4.x + acc[jj][1]*as4.y + acc[jj][2]*as4.z + acc[jj][3]*as4.w;
        float pd = acc[jj][0]*ad4.x + acc[jj][1]*ad4.y + acc[jj][2]*ad4.z + acc[jj][3]*ad4.w;
#pragma unroll
        for (int o = 1; o < 16; o <<= 1) {
            ps += __shfl_xor_sync(0xffffffffu, ps, o);
            pd += __shfl_xor_sync(0xffffffffu, pd, o);
        }
        if ((t & 15) == 0) {
            const int head = c4 >> 4;
            red_s[(4*nq+jj)*4 + head] = ps;
            red_d[(4*nq+jj)*4 + head] = pd;
        }
    }
    __syncthreads();

    // tr overlay on the ws double buffer: [32 nodes][260], tf32-rounded
    float* tr = (float*)(smp + SMP_TR);
#pragma unroll
    for (int jj = 0; jj < 4; ++jj) {
        float4 v;
        v.x = __uint_as_float(tf32u(acc[jj][0]));
        v.y = __uint_as_float(tf32u(acc[jj][1]));
        v.z = __uint_as_float(tf32u(acc[jj][2]));
        v.w = __uint_as_float(tf32u(acc[jj][3]));
        *(float4*)&tr[(4*nq+jj)*260 + 4*c4] = v;
    }
    if (t < 128) {
        const int n = t >> 2, h = t & 3;
        g_ss[(size_t)(bn0+n)*Hh + h] = red_s[n*4 + h];
        g_sd[(size_t)(bn0+n)*Hh + h] = red_d[n*4 + h];
    }
    __syncthreads();

    // store pair-layout tiles to g_hT2
    const int b  = bn0 >> 11;
    const int nl = bn0 & (Nn-1);
    const int T  = nl >> 6;
    const int s0 = (nl & 63) >> 3;      // 0 or 4
    float* dst = g_hT2 + ((size_t)(b*32 + T))*16384;
#pragma unroll
    for (int rep = 0; rep < 2; ++rep) {
        const int u = t + rep*512;      // 0..1023
        const int ch = u & 255, s_rel = u >> 8;   // s_rel 0..3
        float v[8];
#pragma unroll
        for (int k = 0; k < 8; ++k) {
            const int qq = k >> 1, hf = k & 1;
            v[k] = tr[(8*s_rel + qq + 4*hf)*260 + ch];
        }
        const int s = s0 + s_rel;
        const int hx = ch >> 6, c = ch & 63;
        float* p = dst + (((hx*8 + s)*64 + c) << 3);
        *(float4*)p       = make_float4(v[0], v[1], v[2], v[3]);
        *(float4*)(p + 4) = make_float4(v[4], v[5], v[6], v[7]);
    }
}

// ---------------- Kernel B: pipelined fragment-native P + mma.sync tf32 (512 thr) ----------------
__global__ __launch_bounds__(512, 1) void gat_mma_kernel(const float* __restrict__ A)
{
    extern __shared__ char sm[];
    const uint32_t smb = smem_u32(sm);

    const int t    = threadIdx.x;
    const int w    = t >> 5, lane = t & 31;    // 16 warps
    const int h    = w & 3;                    // head
    const int hf   = w >> 2;                   // i-quarter (0..3)
    const int rL   = lane >> 2, q = lane & 3;

    const int cta   = blockIdx.x;
    const int split = cta & 3, ib = cta >> 2;
    const int b     = ib >> 4;
    const int i0    = (ib & 15) * MI;
    const int jbase = split * JR;

    float ssh[2][2];
#pragma unroll
    for (int g = 0; g < 2; ++g)
#pragma unroll
        for (int rh = 0; rh < 2; ++rh)
            ssh[g][rh] = g_ss[((size_t)b*Nn + i0 + hf*32 + 16*g + rL + 8*rh)*Hh + h];

    float acc[2][8][4];
#pragma unroll
    for (int g = 0; g < 2; ++g)
#pragma unroll
        for (int n = 0; n < 8; ++n)
#pragma unroll
            for (int u = 0; u < 4; ++u) acc[g][n][u] = 0.f;
    float lacc[2][2] = {{0.f,0.f},{0.f,0.f}};

    // ---- async stage of tile tt into buffer st ----
    auto stage = [&](int tt, int st) {
        const int j0 = jbase + tt*64;
        const char* srcB = (const char*)(g_hT2 + (size_t)(b*32 + split*8 + tt)*16384);
#pragma unroll
        for (int k = 0; k < 8; ++k) {
            const int u = t + k*512;
            cp16(smb + SMB_B(st) + u*16, srcB + u*16);
        }
#pragma unroll
        for (int k = 0; k < 4; ++k) {
            const int u = t + k*512;               // 0..2047
            const int i = u >> 4, jj = u & 15;
            cp16(smb + SMB_A(st) + i*272 + jj*16,
                 (const char*)(A + ((size_t)b*Nn + i0 + i)*Nn + j0) + jj*16);
        }
        if (t < 64)
            cp16(smb + SMB_S(st) + t*16,
                 (const char*)(g_sd + ((size_t)b*Nn + j0)*Hh) + t*16);
        CP_COMMIT();
    };

    stage(0, 0);

    for (int tt = 0; tt < NT; ++tt) {
        const int st = tt & 1;
        if (tt + 1 < NT) { stage(tt + 1, st ^ 1); CP_WAIT(1); }
        else             { CP_WAIT(0); }
        __syncthreads();

        const float2* sB  = (const float2*)(sm + SMB_B(st));
        const float*  sAf = (const float*)(sm + SMB_A(st));
        const float*  sSD = (const float*)(sm + SMB_S(st));

#pragma unroll
        for (int s = 0; s < 8; ++s) {
            float2 bf[8];
            const float2* bp = sB + ((h*8 + s)*64 + rL)*4 + q;
#pragma unroll
            for (int n = 0; n < 8; ++n) bf[n] = bp[n*32];
            const float sdx = sSD[(8*s + q)*4 + h];
            const float sdy = sSD[(8*s + q + 4)*4 + h];

#pragma unroll
            for (int g = 0; g < 2; ++g) {
                const int iA = hf*32 + 16*g + rL;
                const float a00 = sAf[iA*68 + 8*s + q];
                const float a01 = sAf[iA*68 + 8*s + q + 4];
                const float a10 = sAf[(iA+8)*68 + 8*s + q];
                const float a11 = sAf[(iA+8)*68 + 8*s + q + 4];
                float l00 = ssh[g][0] + sdx;
                float l01 = ssh[g][0] + sdy;
                float l10 = ssh[g][1] + sdx;
                float l11 = ssh[g][1] + sdy;
                l00 = fmaxf(l00, 0.2f*l00);
                l01 = fmaxf(l01, 0.2f*l01);
                l10 = fmaxf(l10, 0.2f*l10);
                l11 = fmaxf(l11, 0.2f*l11);
                const float p00 = (a00 != 0.f) ? __expf(l00) : 0.f;
                const float p01 = (a01 != 0.f) ? __expf(l01) : 0.f;
                const float p10 = (a10 != 0.f) ? __expf(l10) : 0.f;
                const float p11 = (a11 != 0.f) ? __expf(l11) : 0.f;
                const unsigned f0 = tf32u(p00);   // (row,   k)
                const unsigned f1 = tf32u(p10);   // (row+8, k)
                const unsigned f2 = tf32u(p01);   // (row,   k+4)
                const unsigned f3 = tf32u(p11);   // (row+8, k+4)
                lacc[g][0] += __uint_as_float(f0) + __uint_as_float(f2);
                lacc[g][1] += __uint_as_float(f1) + __uint_as_float(f3);
#pragma unroll
                for (int n = 0; n < 8; ++n)
                    mma_tf32(acc[g][n][0], acc[g][n][1], acc[g][n][2], acc[g][n][3],
                             f0, f1, f2, f3,
                             __float_as_uint(bf[n].x), __float_as_uint(bf[n].y));
            }
        }
        __syncthreads();   // done reading st before re-stage
    }

    // lsum: reduce over the 4 q-lanes of each quad
#pragma unroll
    for (int g = 0; g < 2; ++g)
#pragma unroll
        for (int rh = 0; rh < 2; ++rh) {
            float v = lacc[g][rh];
            v += __shfl_xor_sync(0xffffffffu, v, 1);
            v += __shfl_xor_sync(0xffffffffu, v, 2);
            if (q == 0)
                g_lsum[((size_t)cta*MI + hf*32 + 16*g + rL + 8*rh)*Hh + h] = v;
        }

    // store partial numerators
    float* gp = g_part + (size_t)cta*MI*HC;
#pragma unroll
    for (int g = 0; g < 2; ++g) {
        const int i = hf*32 + 16*g + rL;
#pragma unroll
        for (int n = 0; n < 8; ++n) {
            const int ch = h*64 + 8*n + 2*q;
            *(float2*)(gp + (size_t)i*HC + ch)     = make_float2(acc[g][n][0], acc[g][n][1]);
            *(float2*)(gp + (size_t)(i+8)*HC + ch) = make_float2(acc[g][n][2], acc[g][n][3]);
        }
    }
}

// ---------------- Kernel C: merge splits + normalize + bias + ELU + LayerNorm ----------------
__global__ __launch_bounds__(256) void merge_kernel(
    const float* __restrict__ bgat, const float* __restrict__ gamma,
    const float* __restrict__ beta, float* __restrict__ out)
{
    const int t = threadIdx.x, w = t >> 5, lane = t & 31;
    const int row = blockIdx.x*8 + w;      // 0..4095
    const int ib = row >> 7, il = row & 127;
    const int hd = lane >> 3;

    float4 n0 = {0,0,0,0}, n1 = {0,0,0,0};
    float ls = 0.f;
#pragma unroll
    for (int s = 0; s < SPLIT; ++s) {
        const int cta = ib*SPLIT + s;
        const float4* p = (const float4*)(g_part + ((size_t)cta*MI + il)*HC + lane*8);
        const float4 x = p[0], y = p[1];
        n0.x += x.x; n0.y += x.y; n0.z += x.z; n0.w += x.w;
        n1.x += y.x; n1.y += y.y; n1.z += y.z; n1.w += y.w;
        ls += g_lsum[((size_t)cta*MI + il)*Hh + hd];
    }
    const float inv = __fdividef(1.f, ls);

    const int ch = lane*8;
    const float4 bgA = *(const float4*)(bgat + ch), bgB = *(const float4*)(bgat + ch + 4);

    float v[8];
    v[0] = fmaf(n0.x, inv, bgA.x); v[1] = fmaf(n0.y, inv, bgA.y);
    v[2] = fmaf(n0.z, inv, bgA.z); v[3] = fmaf(n0.w, inv, bgA.w);
    v[4] = fmaf(n1.x, inv, bgB.x); v[5] = fmaf(n1.y, inv, bgB.y);
    v[6] = fmaf(n1.z, inv, bgB.z); v[7] = fmaf(n1.w, inv, bgB.w);

    float s1 = 0.f, s2 = 0.f;
#pragma unroll
    for (int k = 0; k < 8; ++k) {
        float x = v[k];
        x = x > 0.f ? x : expm1f(x);
        v[k] = x;
        s1 += x;
        s2 = fmaf(x, x, s2);
    }
#pragma unroll
    for (int o = 16; o; o >>= 1) {
        s1 += __shfl_xor_sync(0xffffffffu, s1, o);
        s2 += __shfl_xor_sync(0xffffffffu, s2, o);
    }
    const float mu   = s1 * (1.f/HC);
    const float var  = fmaf(-mu, mu, s2 * (1.f/HC));
    const float rstd = rsqrtf(var + 1e-3f);

    const float4 gaA = *(const float4*)(gamma + ch), gaB = *(const float4*)(gamma + ch + 4);
    const float4 btA = *(const float4*)(beta  + ch), btB = *(const float4*)(beta  + ch + 4);
    float4 o1, o2;
    o1.x = fmaf((v[0]-mu)*rstd, gaA.x, btA.x); o1.y = fmaf((v[1]-mu)*rstd, gaA.y, btA.y);
    o1.z = fmaf((v[2]-mu)*rstd, gaA.z, btA.z); o1.w = fmaf((v[3]-mu)*rstd, gaA.w, btA.w);
    o2.x = fmaf((v[4]-mu)*rstd, gaB.x, btB.x); o2.y = fmaf((v[5]-mu)*rstd, gaB.y, btB.y);
    o2.z = fmaf((v[6]-mu)*rstd, gaB.z, btB.z); o2.w = fmaf((v[7]-mu)*rstd, gaB.w, btB.w);
    *(float4*)(out + (size_t)row*HC + ch)     = o1;
    *(float4*)(out + (size_t)row*HC + ch + 4) = o2;
}

extern "C" void kernel_launch(void* const* d_in, const int* in_sizes, int n_in,
                              void* d_out, int out_size)
{
    (void)in_sizes; (void)n_in; (void)out_size;
    const float* X      = (const float*)d_in[0];
    const float* A      = (const float*)d_in[1];
    // d_in[2..4] (E, W_edge, b_edge) are dead: sigmoid>0 always => A*gate==0 <=> A==0.
    const float* W_gat  = (const float*)d_in[5];
    const float* a_src  = (const float*)d_in[6];
    const float* a_dst  = (const float*)d_in[7];
    const float* b_gat  = (const float*)d_in[8];
    const float* gamma  = (const float*)d_in[9];
    const float* beta   = (const float*)d_in[10];
    float* out = (float*)d_out;

    cudaFuncSetAttribute(precompute_kernel, cudaFuncAttributeMaxDynamicSharedMemorySize, SMP_TOT);
    cudaFuncSetAttribute(gat_mma_kernel, cudaFuncAttributeMaxDynamicSharedMemorySize, SMB_TOT);

    precompute_kernel<<<(Bb*Nn)/32, 512, SMP_TOT>>>(X, W_gat, a_src, a_dst);
    gat_mma_kernel<<<NCTA, 512, SMB_TOT>>>(A);
    merge_kernel<<<(Bb*Nn)/8, 256>>>(b_gat, gamma, beta, out);
}

// round 7
// speedup vs baseline: 8.9345x; 1.0940x over previous
#include <cuda_runtime.h>
#include <cstdint>

#define Bb 2
#define Nn 2048
#define Ff 128
#define Hh 4
#define HC 256
#define MI 128
#define SPLIT 4
#define JR (Nn/SPLIT)            // 512 j per CTA
#define NT (JR/64)               // 8 j-tiles
#define NCTA ((Bb*Nn/MI)*SPLIT)  // 128

// kernel-B dynamic smem layout (bytes): double-buffered
#define SMB_B(st)  ((st)*65536)                  // h-tile: 16384 floats/stage
#define SMB_A(st)  (131072 + (st)*34816)         // A-tile: [128][68] floats/stage
#define SMB_S(st)  (200704 + (st)*2048)          // (Eb,Fb)-tile: [64][4] float2/stage
#define SMB_TOT    204800

// precompute dynamic smem layout (bytes)
#define SMP_XS     0                             // [16][128] floats = 8192
#define SMP_WS(st) (8192 + (st)*32768)           // [32][256] floats per stage
#define SMP_RS     73728                         // [16][4]
#define SMP_RD     73984
#define SMP_TOT    74240
#define SMP_TR     8192                          // tr overlay on ws0 after GEMM

// device scratch (allocation-free)
__device__ float  g_hT2[Bb*(Nn/64)*16384];    // [b][T][h][s][c][q][half], tf32 (4 MB)
__device__ float2 g_sE [Bb*Nn*Hh];            // (exp(ss), exp(0.2 ss)) per (node, head)
__device__ float2 g_dE [Bb*Nn*Hh];            // (exp(sd), exp(0.2 sd))
__device__ float  g_part[(size_t)NCTA*MI*HC]; // 16.8 MB partial numerators
__device__ float  g_lsum[NCTA*MI*Hh];

__device__ __forceinline__ unsigned tf32u(float x) {
    unsigned u; asm("cvt.rna.tf32.f32 %0, %1;" : "=r"(u) : "f"(x)); return u;
}
__device__ __forceinline__ void mma_tf32(float& d0, float& d1, float& d2, float& d3,
                                         unsigned a0, unsigned a1, unsigned a2, unsigned a3,
                                         unsigned b0, unsigned b1) {
    asm volatile("mma.sync.aligned.m16n8k8.row.col.f32.tf32.tf32.f32 "
                 "{%0,%1,%2,%3}, {%4,%5,%6,%7}, {%8,%9}, {%0,%1,%2,%3};"
                 : "+f"(d0), "+f"(d1), "+f"(d2), "+f"(d3)
                 : "r"(a0), "r"(a1), "r"(a2), "r"(a3), "r"(b0), "r"(b1));
}
__device__ __forceinline__ uint32_t smem_u32(const void* p) {
    uint32_t a;
    asm("{ .reg .u64 t; cvta.to.shared.u64 t, %1; cvt.u32.u64 %0, t; }" : "=r"(a) : "l"(p));
    return a;
}
__device__ __forceinline__ void cp16(uint32_t dst, const void* src) {
    asm volatile("cp.async.cg.shared.global [%0], [%1], 16;" :: "r"(dst), "l"(src));
}
#define CP_COMMIT() asm volatile("cp.async.commit_group;" ::: "memory")
#define CP_WAIT(n)  asm volatile("cp.async.wait_group %0;" :: "n"(n) : "memory")

// ---------------- Kernel A: h = X @ W_gat -> g_hT2 ; exp pairs ----------------
__global__ __launch_bounds__(512, 2) void precompute_kernel(
    const float* __restrict__ X, const float* __restrict__ Wg,
    const float* __restrict__ asrc, const float* __restrict__ adst)
{
    extern __shared__ char smp[];
    float* xs    = (float*)(smp + SMP_XS);      // [16][128]
    float* red_s = (float*)(smp + SMP_RS);      // [16][4]
    float* red_d = (float*)(smp + SMP_RD);

    const int t   = threadIdx.x;                // 0..511
    const int bn0 = blockIdx.x * 16;
    const int c4  = t & 63;                     // channel quad
    const int np  = t >> 6;                     // node pair (0..7)
    const uint32_t smb = smem_u32(smp);

    // stage X [16][128]
    {
        const int n = t >> 5, f4 = t & 31;
        *(float4*)&xs[n*Ff + f4*4] = *(const float4*)(X + (size_t)(bn0+n)*Ff + f4*4);
    }

    auto stageW = [&](int fc, int st) {
#pragma unroll
        for (int k = 0; k < 4; ++k) {
            const int u = t + k*512;            // 0..2047 float4s
            const int lf = u >> 6, cq = u & 63;
            const int hh = cq >> 4, cl = cq & 15;
            cp16(smb + SMP_WS(st) + (lf*256 + cq*4)*4,
                 Wg + (size_t)hh*(Ff*64) + (size_t)(fc+lf)*64 + cl*4);
        }
        CP_COMMIT();
    };

    float acc[2][4];
#pragma unroll
    for (int jj = 0; jj < 2; ++jj)
#pragma unroll
        for (int cc = 0; cc < 4; ++cc) acc[jj][cc] = 0.f;

    stageW(0, 0);
    for (int ch = 0; ch < 4; ++ch) {
        const int st = ch & 1;
        if (ch + 1 < 4) { stageW(32*(ch+1), st ^ 1); CP_WAIT(1); }
        else            { CP_WAIT(0); }
        __syncthreads();
        const float* ws = (const float*)(smp + SMP_WS(st));
#pragma unroll
        for (int lf = 0; lf < 32; ++lf) {
            const float4 w4 = *(const float4*)&ws[lf*256 + 4*c4];
            const float x0 = xs[(2*np+0)*Ff + 32*ch + lf];
            const float x1 = xs[(2*np+1)*Ff + 32*ch + lf];
            acc[0][0] = fmaf(x0, w4.x, acc[0][0]); acc[0][1] = fmaf(x0, w4.y, acc[0][1]);
            acc[0][2] = fmaf(x0, w4.z, acc[0][2]); acc[0][3] = fmaf(x0, w4.w, acc[0][3]);
            acc[1][0] = fmaf(x1, w4.x, acc[1][0]); acc[1][1] = fmaf(x1, w4.y, acc[1][1]);
            acc[1][2] = fmaf(x1, w4.z, acc[1][2]); acc[1][3] = fmaf(x1, w4.w, acc[1][3]);
        }
        __syncthreads();
    }

    // s_src/s_dst partials over this thread's 4 channels; reduce over the 16
    // c4-lanes of the same head (aligned 16-lane groups)
    const float4 as4 = *(const float4*)(asrc + 4*c4);
    const float4 ad4 = *(const float4*)(adst + 4*c4);
#pragma unroll
    for (int jj = 0; jj < 2; ++jj) {
        float ps = acc[jj][0]*as4.x + acc[jj][1]*as4.y + acc[jj][2]*as4.z + acc[jj][3]*as4.w;
        float pd = acc[jj][0]*ad4.x + acc[jj][1]*ad4.y + acc[jj][2]*ad4.z + acc[jj][3]*ad4.w;
#pragma unroll
        for (int o = 1; o < 16; o <<= 1) {
            ps += __shfl_xor_sync(0xffffffffu, ps, o);
            pd += __shfl_xor_sync(0xffffffffu, pd, o);
        }
        if ((t & 15) == 0) {
            const int head = c4 >> 4;
            red_s[(2*np+jj)*4 + head] = ps;
            red_d[(2*np+jj)*4 + head] = pd;
        }
    }
    __syncthreads();

    // tr overlay on ws0: [16 nodes][260], tf32-rounded
    float* tr = (float*)(smp + SMP_TR);
#pragma unroll
    for (int jj = 0; jj < 2; ++jj) {
        float4 v;
        v.x = __uint_as_float(tf32u(acc[jj][0]));
        v.y = __uint_as_float(tf32u(acc[jj][1]));
        v.z = __uint_as_float(tf32u(acc[jj][2]));
        v.w = __uint_as_float(tf32u(acc[jj][3]));
        *(float4*)&tr[(2*np+jj)*260 + 4*c4] = v;
    }
    if (t < 64) {
        const int n = t >> 2, h = t & 3;
        const float ss = red_s[n*4 + h];
        const float sd = red_d[n*4 + h];
        g_sE[(size_t)(bn0+n)*Hh + h] = make_float2(__expf(ss), __expf(0.2f*ss));
        g_dE[(size_t)(bn0+n)*Hh + h] = make_float2(__expf(sd), __expf(0.2f*sd));
    }
    __syncthreads();

    // store pair-layout tiles to g_hT2: 512 jobs = 256 ch x 2 s-groups
    const int b  = bn0 >> 11;
    const int nl = bn0 & (Nn-1);
    const int T  = nl >> 6;
    const int s0 = (nl & 63) >> 3;      // 0,2,4,6
    float* dst = g_hT2 + ((size_t)(b*32 + T))*16384;
    {
        const int ch = t & 255, s_rel = t >> 8;   // s_rel 0..1
        float v[8];
#pragma unroll
        for (int k = 0; k < 8; ++k) {
            const int qq = k >> 1, hf = k & 1;
            v[k] = tr[(8*s_rel + qq + 4*hf)*260 + ch];
        }
        const int s = s0 + s_rel;
        const int hx = ch >> 6, c = ch & 63;
        float* p = dst + (((hx*8 + s)*64 + c) << 3);
        *(float4*)p       = make_float4(v[0], v[1], v[2], v[3]);
        *(float4*)(p + 4) = make_float4(v[4], v[5], v[6], v[7]);
    }
}

// ---------------- Kernel B: MUFU-free P + mma.sync tf32 (1024 thr, 32 warps) ----------------
__global__ __launch_bounds__(1024, 1) void gat_mma_kernel(const float* __restrict__ A)
{
    extern __shared__ char sm[];
    const uint32_t smb = smem_u32(sm);

    const int t    = threadIdx.x;
    const int w    = t >> 5, lane = t & 31;    // 32 warps
    const int h    = w & 3;                    // head
    const int o8   = w >> 2;                   // i-octant (0..7): rows o8*16..+15
    const int rL   = lane >> 2, q = lane & 3;
    const int iA   = o8*16 + rL;

    const int cta   = blockIdx.x;
    const int split = cta & 3, ib = cta >> 2;
    const int b     = ib >> 4;
    const int i0    = (ib & 15) * MI;
    const int jbase = split * JR;

    // (Ea, Fa) for rows iA, iA+8
    float2 ea[2];
#pragma unroll
    for (int rh = 0; rh < 2; ++rh)
        ea[rh] = g_sE[((size_t)b*Nn + i0 + iA + 8*rh)*Hh + h];

    float acc[8][4];
#pragma unroll
    for (int n = 0; n < 8; ++n)
#pragma unroll
        for (int u = 0; u < 4; ++u) acc[n][u] = 0.f;
    float lacc[2] = {0.f, 0.f};

    // ---- async stage of tile tt into buffer st ----
    auto stage = [&](int tt, int st) {
        const int j0 = jbase + tt*64;
        const char* srcB = (const char*)(g_hT2 + (size_t)(b*32 + split*8 + tt)*16384);
#pragma unroll
        for (int k = 0; k < 4; ++k) {
            const int u = t + k*1024;
            cp16(smb + SMB_B(st) + u*16, srcB + u*16);
        }
#pragma unroll
        for (int k = 0; k < 2; ++k) {
            const int u = t + k*1024;              // 0..2047
            const int i = u >> 4, jj = u & 15;
            cp16(smb + SMB_A(st) + i*272 + jj*16,
                 (const char*)(A + ((size_t)b*Nn + i0 + i)*Nn + j0) + jj*16);
        }
        if (t < 128)
            cp16(smb + SMB_S(st) + t*16,
                 (const char*)(g_dE + ((size_t)b*Nn + j0)*Hh) + t*16);
        CP_COMMIT();
    };

    stage(0, 0);

    for (int tt = 0; tt < NT; ++tt) {
        const int st = tt & 1;
        if (tt + 1 < NT) { stage(tt + 1, st ^ 1); CP_WAIT(1); }
        else             { CP_WAIT(0); }
        __syncthreads();

        const float2* sB  = (const float2*)(sm + SMB_B(st));
        const float*  sAf = (const float*)(sm + SMB_A(st));
        const float2* sEB = (const float2*)(sm + SMB_S(st));

#pragma unroll
        for (int s = 0; s < 8; ++s) {
            // (Eb, Fb) for j = 8s+q and 8s+q+4
            const float2 eb0 = sEB[(8*s + q)*4 + h];
            const float2 eb1 = sEB[(8*s + q + 4)*4 + h];
            // adjacency mask values
            const float a00 = sAf[iA*68 + 8*s + q];
            const float a01 = sAf[iA*68 + 8*s + q + 4];
            const float a10 = sAf[(iA+8)*68 + 8*s + q];
            const float a11 = sAf[(iA+8)*68 + 8*s + q + 4];
            // p = exp(leaky(ss+sd)) = max(Ea*Eb, Fa*Fb);  masked to 0 where A==0
            float p00 = fmaxf(ea[0].x*eb0.x, ea[0].y*eb0.y);
            float p10 = fmaxf(ea[1].x*eb0.x, ea[1].y*eb0.y);
            float p01 = fmaxf(ea[0].x*eb1.x, ea[0].y*eb1.y);
            float p11 = fmaxf(ea[1].x*eb1.x, ea[1].y*eb1.y);
            p00 = (a00 != 0.f) ? p00 : 0.f;
            p10 = (a10 != 0.f) ? p10 : 0.f;
            p01 = (a01 != 0.f) ? p01 : 0.f;
            p11 = (a11 != 0.f) ? p11 : 0.f;
            const unsigned f0 = tf32u(p00);   // (row,   k)
            const unsigned f1 = tf32u(p10);   // (row+8, k)
            const unsigned f2 = tf32u(p01);   // (row,   k+4)
            const unsigned f3 = tf32u(p11);   // (row+8, k+4)
            lacc[0] += __uint_as_float(f0) + __uint_as_float(f2);
            lacc[1] += __uint_as_float(f1) + __uint_as_float(f3);

            const float2* bp = sB + ((h*8 + s)*64 + rL)*4 + q;
#pragma unroll
            for (int n = 0; n < 8; ++n) {
                const float2 bv = bp[n*32];
                mma_tf32(acc[n][0], acc[n][1], acc[n][2], acc[n][3],
                         f0, f1, f2, f3,
                         __float_as_uint(bv.x), __float_as_uint(bv.y));
            }
        }
        __syncthreads();   // done reading st before re-stage
    }

    // lsum: reduce over the 4 q-lanes of each quad
#pragma unroll
    for (int rh = 0; rh < 2; ++rh) {
        float v = lacc[rh];
        v += __shfl_xor_sync(0xffffffffu, v, 1);
        v += __shfl_xor_sync(0xffffffffu, v, 2);
        if (q == 0)
            g_lsum[((size_t)cta*MI + iA + 8*rh)*Hh + h] = v;
    }

    // store partial numerators
    float* gp = g_part + (size_t)cta*MI*HC;
#pragma unroll
    for (int n = 0; n < 8; ++n) {
        const int ch = h*64 + 8*n + 2*q;
        *(float2*)(gp + (size_t)iA*HC + ch)     = make_float2(acc[n][0], acc[n][1]);
        *(float2*)(gp + (size_t)(iA+8)*HC + ch) = make_float2(acc[n][2], acc[n][3]);
    }
}

// ---------------- Kernel C: merge splits + normalize + bias + ELU + LayerNorm ----------------
__global__ __launch_bounds__(256) void merge_kernel(
    const float* __restrict__ bgat, const float* __restrict__ gamma,
    const float* __restrict__ beta, float* __restrict__ out)
{
    const int t = threadIdx.x, w = t >> 5, lane = t & 31;
    const int row = blockIdx.x*8 + w;      // 0..4095
    const int ib = row >> 7, il = row & 127;
    const int hd = lane >> 3;

    float4 n0 = {0,0,0,0}, n1 = {0,0,0,0};
    float ls = 0.f;
#pragma unroll
    for (int s = 0; s < SPLIT; ++s) {
        const int cta = ib*SPLIT + s;
        const float4* p = (const float4*)(g_part + ((size_t)cta*MI + il)*HC + lane*8);
        const float4 x = p[0], y = p[1];
        n0.x += x.x; n0.y += x.y; n0.z += x.z; n0.w += x.w;
        n1.x += y.x; n1.y += y.y; n1.z += y.z; n1.w += y.w;
        ls += g_lsum[((size_t)cta*MI + il)*Hh + hd];
    }
    const float inv = __fdividef(1.f, ls);

    const int ch = lane*8;
    const float4 bgA = *(const float4*)(bgat + ch), bgB = *(const float4*)(bgat + ch + 4);

    float v[8];
    v[0] = fmaf(n0.x, inv, bgA.x); v[1] = fmaf(n0.y, inv, bgA.y);
    v[2] = fmaf(n0.z, inv, bgA.z); v[3] = fmaf(n0.w, inv, bgA.w);
    v[4] = fmaf(n1.x, inv, bgB.x); v[5] = fmaf(n1.y, inv, bgB.y);
    v[6] = fmaf(n1.z, inv, bgB.z); v[7] = fmaf(n1.w, inv, bgB.w);

    float s1 = 0.f, s2 = 0.f;
#pragma unroll
    for (int k = 0; k < 8; ++k) {
        float x = v[k];
        x = x > 0.f ? x : expm1f(x);
        v[k] = x;
        s1 += x;
        s2 = fmaf(x, x, s2);
    }
#pragma unroll
    for (int o = 16; o; o >>= 1) {
        s1 += __shfl_xor_sync(0xffffffffu, s1, o);
        s2 += __shfl_xor_sync(0xffffffffu, s2, o);
    }
    const float mu   = s1 * (1.f/HC);
    const float var  = fmaf(-mu, mu, s2 * (1.f/HC));
    const float rstd = rsqrtf(var + 1e-3f);

    const float4 gaA = *(const float4*)(gamma + ch), gaB = *(const float4*)(gamma + ch + 4);
    const float4 btA = *(const float4*)(beta  + ch), btB = *(const float4*)(beta  + ch + 4);
    float4 o1, o2;
    o1.x = fmaf((v[0]-mu)*rstd, gaA.x, btA.x); o1.y = fmaf((v[1]-mu)*rstd, gaA.y, btA.y);
    o1.z = fmaf((v[2]-mu)*rstd, gaA.z, btA.z); o1.w = fmaf((v[3]-mu)*rstd, gaA.w, btA.w);
    o2.x = fmaf((v[4]-mu)*rstd, gaB.x, btB.x); o2.y = fmaf((v[5]-mu)*rstd, gaB.y, btB.y);
    o2.z = fmaf((v[6]-mu)*rstd, gaB.z, btB.z); o2.w = fmaf((v[7]-mu)*rstd, gaB.w, btB.w);
    *(float4*)(out + (size_t)row*HC + ch)     = o1;
    *(float4*)(out + (size_t)row*HC + ch + 4) = o2;
}

extern "C" void kernel_launch(void* const* d_in, const int* in_sizes, int n_in,
                              void* d_out, int out_size)
{
    (void)in_sizes; (void)n_in; (void)out_size;
    const float* X      = (const float*)d_in[0];
    const float* A      = (const float*)d_in[1];
    // d_in[2..4] (E, W_edge, b_edge) are dead: sigmoid>0 always => A*gate==0 <=> A==0.
    const float* W_gat  = (const float*)d_in[5];
    const float* a_src  = (const float*)d_in[6];
    const float* a_dst  = (const float*)d_in[7];
    const float* b_gat  = (const float*)d_in[8];
    const float* gamma  = (const float*)d_in[9];
    const float* beta   = (const float*)d_in[10];
    float* out = (float*)d_out;

    cudaFuncSetAttribute(precompute_kernel, cudaFuncAttributeMaxDynamicSharedMemorySize, SMP_TOT);
    cudaFuncSetAttribute(gat_mma_kernel, cudaFuncAttributeMaxDynamicSharedMemorySize, SMB_TOT);

    precompute_kernel<<<(Bb*Nn)/16, 512, SMP_TOT>>>(X, W_gat, a_src, a_dst);
    gat_mma_kernel<<<NCTA, 1024, SMB_TOT>>>(A);
    merge_kernel<<<(Bb*Nn)/8, 256>>>(b_gat, gamma, beta, out);
}

// round 8
// speedup vs baseline: 8.9434x; 1.0010x over previous
#include <cuda_runtime.h>
#include <cstdint>

#define Bb 2
#define Nn 2048
#define Ff 128
#define Hh 4
#define HC 256
#define MI 128
#define SPLIT 4
#define JR (Nn/SPLIT)            // 512 j per CTA
#define NT (JR/64)               // 8 j-tiles
#define NCTA ((Bb*Nn/MI)*SPLIT)  // 128

// kernel-B dynamic smem layout (bytes): double-buffered
#define SMB_B(st)  ((st)*65536)                  // h-tile: 16384 floats/stage
#define SMB_A(st)  (131072 + (st)*34816)         // A-tile: [128][68] floats/stage
#define SMB_S(st)  (200704 + (st)*2048)          // (Eb,Fb)-tile: [64][4] float2/stage
#define SMB_TOT    204800

// precompute dynamic smem layout (bytes)
#define SMP_XS     0                             // [16][128] floats = 8192
#define SMP_WS(st) (8192 + (st)*32768)           // [32][256] floats per stage
#define SMP_RS     73728                         // [16][4]
#define SMP_RD     73984
#define SMP_TOT    74240
#define SMP_TR     8192                          // tr overlay on ws0 after GEMM

// device scratch (allocation-free)
__device__ float  g_hT2[Bb*(Nn/64)*16384];    // [b][T][h][s][c][q][half], tf32 (4 MB)
__device__ float2 g_sE [Bb*Nn*Hh];            // (exp(ss), exp(0.2 ss)) per (node, head)
__device__ float2 g_dE [Bb*Nn*Hh];            // (exp(sd), exp(0.2 sd))
__device__ float  g_part[(size_t)NCTA*MI*HC]; // 16.8 MB partial numerators
__device__ float  g_lsum[NCTA*MI*Hh];

__device__ __forceinline__ unsigned tf32u(float x) {
    unsigned u; asm("cvt.rna.tf32.f32 %0, %1;" : "=r"(u) : "f"(x)); return u;
}
__device__ __forceinline__ void mma_tf32(float& d0, float& d1, float& d2, float& d3,
                                         unsigned a0, unsigned a1, unsigned a2, unsigned a3,
                                         unsigned b0, unsigned b1) {
    asm volatile("mma.sync.aligned.m16n8k8.row.col.f32.tf32.tf32.f32 "
                 "{%0,%1,%2,%3}, {%4,%5,%6,%7}, {%8,%9}, {%0,%1,%2,%3};"
                 : "+f"(d0), "+f"(d1), "+f"(d2), "+f"(d3)
                 : "r"(a0), "r"(a1), "r"(a2), "r"(a3), "r"(b0), "r"(b1));
}
__device__ __forceinline__ uint32_t smem_u32(const void* p) {
    uint32_t a;
    asm("{ .reg .u64 t; cvta.to.shared.u64 t, %1; cvt.u32.u64 %0, t; }" : "=r"(a) : "l"(p));
    return a;
}
__device__ __forceinline__ void cp16(uint32_t dst, const void* src) {
    asm volatile("cp.async.cg.shared.global [%0], [%1], 16;" :: "r"(dst), "l"(src));
}
#define CP_COMMIT() asm volatile("cp.async.commit_group;" ::: "memory")
#define CP_WAIT(n)  asm volatile("cp.async.wait_group %0;" :: "n"(n) : "memory")

// ---------------- Kernel A: h = X @ W_gat -> g_hT2 ; exp pairs ----------------
__global__ __launch_bounds__(512, 2) void precompute_kernel(
    const float* __restrict__ X, const float* __restrict__ Wg,
    const float* __restrict__ asrc, const float* __restrict__ adst)
{
    extern __shared__ char smp[];
    float* xs    = (float*)(smp + SMP_XS);      // [16][128]
    float* red_s = (float*)(smp + SMP_RS);      // [16][4]
    float* red_d = (float*)(smp + SMP_RD);

    const int t   = threadIdx.x;                // 0..511
    const int bn0 = blockIdx.x * 16;
    const int c4  = t & 63;                     // channel quad
    const int np  = t >> 6;                     // node pair (0..7)
    const uint32_t smb = smem_u32(smp);

    // stage X [16][128]
    {
        const int n = t >> 5, f4 = t & 31;
        *(float4*)&xs[n*Ff + f4*4] = *(const float4*)(X + (size_t)(bn0+n)*Ff + f4*4);
    }

    auto stageW = [&](int fc, int st) {
#pragma unroll
        for (int k = 0; k < 4; ++k) {
            const int u = t + k*512;            // 0..2047 float4s
            const int lf = u >> 6, cq = u & 63;
            const int hh = cq >> 4, cl = cq & 15;
            cp16(smb + SMP_WS(st) + (lf*256 + cq*4)*4,
                 Wg + (size_t)hh*(Ff*64) + (size_t)(fc+lf)*64 + cl*4);
        }
        CP_COMMIT();
    };

    float acc[2][4];
#pragma unroll
    for (int jj = 0; jj < 2; ++jj)
#pragma unroll
        for (int cc = 0; cc < 4; ++cc) acc[jj][cc] = 0.f;

    stageW(0, 0);
    for (int ch = 0; ch < 4; ++ch) {
        const int st = ch & 1;
        if (ch + 1 < 4) { stageW(32*(ch+1), st ^ 1); CP_WAIT(1); }
        else            { CP_WAIT(0); }
        __syncthreads();
        const float* ws = (const float*)(smp + SMP_WS(st));
#pragma unroll
        for (int lf = 0; lf < 32; ++lf) {
            const float4 w4 = *(const float4*)&ws[lf*256 + 4*c4];
            const float x0 = xs[(2*np+0)*Ff + 32*ch + lf];
            const float x1 = xs[(2*np+1)*Ff + 32*ch + lf];
            acc[0][0] = fmaf(x0, w4.x, acc[0][0]); acc[0][1] = fmaf(x0, w4.y, acc[0][1]);
            acc[0][2] = fmaf(x0, w4.z, acc[0][2]); acc[0][3] = fmaf(x0, w4.w, acc[0][3]);
            acc[1][0] = fmaf(x1, w4.x, acc[1][0]); acc[1][1] = fmaf(x1, w4.y, acc[1][1]);
            acc[1][2] = fmaf(x1, w4.z, acc[1][2]); acc[1][3] = fmaf(x1, w4.w, acc[1][3]);
        }
        __syncthreads();
    }

    // s_src/s_dst partials over this thread's 4 channels; reduce over the 16
    // c4-lanes of the same head (aligned 16-lane groups)
    const float4 as4 = *(const float4*)(asrc + 4*c4);
    const float4 ad4 = *(const float4*)(adst + 4*c4);
#pragma unroll
    for (int jj = 0; jj < 2; ++jj) {
        float ps = acc[jj][0]*as4.x + acc[jj][1]*as4.y + acc[jj][2]*as4.z + acc[jj][3]*as4.w;
        float pd = acc[jj][0]*ad4.x + acc[jj][1]*ad4.y + acc[jj][2]*ad4.z + acc[jj][3]*ad4.w;
#pragma unroll
        for (int o = 1; o < 16; o <<= 1) {
            ps += __shfl_xor_sync(0xffffffffu, ps, o);
            pd += __shfl_xor_sync(0xffffffffu, pd, o);
        }
        if ((t & 15) == 0) {
            const int head = c4 >> 4;
            red_s[(2*np+jj)*4 + head] = ps;
            red_d[(2*np+jj)*4 + head] = pd;
        }
    }
    __syncthreads();

    // tr overlay on ws0: [16 nodes][260], tf32-rounded
    float* tr = (float*)(smp + SMP_TR);
#pragma unroll
    for (int jj = 0; jj < 2; ++jj) {
        float4 v;
        v.x = __uint_as_float(tf32u(acc[jj][0]));
        v.y = __uint_as_float(tf32u(acc[jj][1]));
        v.z = __uint_as_float(tf32u(acc[jj][2]));
        v.w = __uint_as_float(tf32u(acc[jj][3]));
        *(float4*)&tr[(2*np+jj)*260 + 4*c4] = v;
    }
    if (t < 64) {
        const int n = t >> 2, h = t & 3;
        const float ss = red_s[n*4 + h];
        const float sd = red_d[n*4 + h];
        g_sE[(size_t)(bn0+n)*Hh + h] = make_float2(__expf(ss), __expf(0.2f*ss));
        g_dE[(size_t)(bn0+n)*Hh + h] = make_float2(__expf(sd), __expf(0.2f*sd));
    }
    __syncthreads();

    // store pair-layout tiles to g_hT2: 512 jobs = 256 ch x 2 s-groups
    const int b  = bn0 >> 11;
    const int nl = bn0 & (Nn-1);
    const int T  = nl >> 6;
    const int s0 = (nl & 63) >> 3;      // 0,2,4,6
    float* dst = g_hT2 + ((size_t)(b*32 + T))*16384;
    {
        const int ch = t & 255, s_rel = t >> 8;   // s_rel 0..1
        float v[8];
#pragma unroll
        for (int k = 0; k < 8; ++k) {
            const int qq = k >> 1, hf = k & 1;
            v[k] = tr[(8*s_rel + qq + 4*hf)*260 + ch];
        }
        const int s = s0 + s_rel;
        const int hx = ch >> 6, c = ch & 63;
        float* p = dst + (((hx*8 + s)*64 + c) << 3);
        *(float4*)p       = make_float4(v[0], v[1], v[2], v[3]);
        *(float4*)(p + 4) = make_float4(v[4], v[5], v[6], v[7]);
    }
}

// ---------------- Kernel B: MUFU-free P + mma.sync tf32 (1024 thr, 32 warps) ----------------
__global__ __launch_bounds__(1024, 1) void gat_mma_kernel(const float* __restrict__ A)
{
    extern __shared__ char sm[];
    const uint32_t smb = smem_u32(sm);

    const int t    = threadIdx.x;
    const int w    = t >> 5, lane = t & 31;    // 32 warps
    const int h    = w & 3;                    // head
    const int o8   = w >> 2;                   // i-octant (0..7): rows o8*16..+15
    const int rL   = lane >> 2, q = lane & 3;
    const int iA   = o8*16 + rL;

    const int cta   = blockIdx.x;
    const int split = cta & 3, ib = cta >> 2;
    const int b     = ib >> 4;
    const int i0    = (ib & 15) * MI;
    const int jbase = split * JR;

    // (Ea, Fa) for rows iA, iA+8
    float2 ea[2];
#pragma unroll
    for (int rh = 0; rh < 2; ++rh)
        ea[rh] = g_sE[((size_t)b*Nn + i0 + iA + 8*rh)*Hh + h];

    float acc[8][4];
#pragma unroll
    for (int n = 0; n < 8; ++n)
#pragma unroll
        for (int u = 0; u < 4; ++u) acc[n][u] = 0.f;
    float lacc[2] = {0.f, 0.f};

    // ---- async stage of tile tt into buffer st ----
    auto stage = [&](int tt, int st) {
        const int j0 = jbase + tt*64;
        const char* srcB = (const char*)(g_hT2 + (size_t)(b*32 + split*8 + tt)*16384);
#pragma unroll
        for (int k = 0; k < 4; ++k) {
            const int u = t + k*1024;
            cp16(smb + SMB_B(st) + u*16, srcB + u*16);
        }
#pragma unroll
        for (int k = 0; k < 2; ++k) {
            const int u = t + k*1024;              // 0..2047
            const int i = u >> 4, jj = u & 15;
            cp16(smb + SMB_A(st) + i*272 + jj*16,
                 (const char*)(A + ((size_t)b*Nn + i0 + i)*Nn + j0) + jj*16);
        }
        if (t < 128)
            cp16(smb + SMB_S(st) + t*16,
                 (const char*)(g_dE + ((size_t)b*Nn + j0)*Hh) + t*16);
        CP_COMMIT();
    };

    stage(0, 0);

    for (int tt = 0; tt < NT; ++tt) {
        const int st = tt & 1;
        if (tt + 1 < NT) { stage(tt + 1, st ^ 1); CP_WAIT(1); }
        else             { CP_WAIT(0); }
        __syncthreads();

        const float2* sB  = (const float2*)(sm + SMB_B(st));
        const float*  sAf = (const float*)(sm + SMB_A(st));
        const float2* sEB = (const float2*)(sm + SMB_S(st));

#pragma unroll
        for (int s = 0; s < 8; ++s) {
            // (Eb, Fb) for j = 8s+q and 8s+q+4
            const float2 eb0 = sEB[(8*s + q)*4 + h];
            const float2 eb1 = sEB[(8*s + q + 4)*4 + h];
            // adjacency mask values
            const float a00 = sAf[iA*68 + 8*s + q];
            const float a01 = sAf[iA*68 + 8*s + q + 4];
            const float a10 = sAf[(iA+8)*68 + 8*s + q];
            const float a11 = sAf[(iA+8)*68 + 8*s + q + 4];
            // p = exp(leaky(ss+sd)) = max(Ea*Eb, Fa*Fb);  masked to 0 where A==0
            float p00 = fmaxf(ea[0].x*eb0.x, ea[0].y*eb0.y);
            float p10 = fmaxf(ea[1].x*eb0.x, ea[1].y*eb0.y);
            float p01 = fmaxf(ea[0].x*eb1.x, ea[0].y*eb1.y);
            float p11 = fmaxf(ea[1].x*eb1.x, ea[1].y*eb1.y);
            p00 = (a00 != 0.f) ? p00 : 0.f;
            p10 = (a10 != 0.f) ? p10 : 0.f;
            p01 = (a01 != 0.f) ? p01 : 0.f;
            p11 = (a11 != 0.f) ? p11 : 0.f;
            const unsigned f0 = tf32u(p00);   // (row,   k)
            const unsigned f1 = tf32u(p10);   // (row+8, k)
            const unsigned f2 = tf32u(p01);   // (row,   k+4)
            const unsigned f3 = tf32u(p11);   // (row+8, k+4)
            lacc[0] += __uint_as_float(f0) + __uint_as_float(f2);
            lacc[1] += __uint_as_float(f1) + __uint_as_float(f3);

            const float2* bp = sB + ((h*8 + s)*64 + rL)*4 + q;
#pragma unroll
            for (int n = 0; n < 8; ++n) {
                const float2 bv = bp[n*32];
                mma_tf32(acc[n][0], acc[n][1], acc[n][2], acc[n][3],
                         f0, f1, f2, f3,
                         __float_as_uint(bv.x), __float_as_uint(bv.y));
            }
        }
        __syncthreads();   // done reading st before re-stage
    }

    // lsum: reduce over the 4 q-lanes of each quad
#pragma unroll
    for (int rh = 0; rh < 2; ++rh) {
        float v = lacc[rh];
        v += __shfl_xor_sync(0xffffffffu, v, 1);
        v += __shfl_xor_sync(0xffffffffu, v, 2);
        if (q == 0)
            g_lsum[((size_t)cta*MI + iA + 8*rh)*Hh + h] = v;
    }

    // store partial numerators
    float* gp = g_part + (size_t)cta*MI*HC;
#pragma unroll
    for (int n = 0; n < 8; ++n) {
        const int ch = h*64 + 8*n + 2*q;
        *(float2*)(gp + (size_t)iA*HC + ch)     = make_float2(acc[n][0], acc[n][1]);
        *(float2*)(gp + (size_t)(iA+8)*HC + ch) = make_float2(acc[n][2], acc[n][3]);
    }
}

// ---------------- Kernel C: merge splits + normalize + bias + ELU + LayerNorm ----------------
__global__ __launch_bounds__(256) void merge_kernel(
    const float* __restrict__ bgat, const float* __restrict__ gamma,
    const float* __restrict__ beta, float* __restrict__ out)
{
    const int t = threadIdx.x, w = t >> 5, lane = t & 31;
    const int row = blockIdx.x*8 + w;      // 0..4095
    const int ib = row >> 7, il = row & 127;
    const int hd = lane >> 3;

    float4 n0 = {0,0,0,0}, n1 = {0,0,0,0};
    float ls = 0.f;
#pragma unroll
    for (int s = 0; s < SPLIT; ++s) {
        const int cta = ib*SPLIT + s;
        const float4* p = (const float4*)(g_part + ((size_t)cta*MI + il)*HC + lane*8);
        const float4 x = p[0], y = p[1];
        n0.x += x.x; n0.y += x.y; n0.z += x.z; n0.w += x.w;
        n1.x += y.x; n1.y += y.y; n1.z += y.z; n1.w += y.w;
        ls += g_lsum[((size_t)cta*MI + il)*Hh + hd];
    }
    const float inv = __fdividef(1.f, ls);

    const int ch = lane*8;
    const float4 bgA = *(const float4*)(bgat + ch), bgB = *(const float4*)(bgat + ch + 4);

    float v[8];
    v[0] = fmaf(n0.x, inv, bgA.x); v[1] = fmaf(n0.y, inv, bgA.y);
    v[2] = fmaf(n0.z, inv, bgA.z); v[3] = fmaf(n0.w, inv, bgA.w);
    v[4] = fmaf(n1.x, inv, bgB.x); v[5] = fmaf(n1.y, inv, bgB.y);
    v[6] = fmaf(n1.z, inv, bgB.z); v[7] = fmaf(n1.w, inv, bgB.w);

    float s1 = 0.f, s2 = 0.f;
#pragma unroll
    for (int k = 0; k < 8; ++k) {
        float x = v[k];
        x = x > 0.f ? x : expm1f(x);
        v[k] = x;
        s1 += x;
        s2 = fmaf(x, x, s2);
    }
#pragma unroll
    for (int o = 16; o; o >>= 1) {
        s1 += __shfl_xor_sync(0xffffffffu, s1, o);
        s2 += __shfl_xor_sync(0xffffffffu, s2, o);
    }
    const float mu   = s1 * (1.f/HC);
    const float var  = fmaf(-mu, mu, s2 * (1.f/HC));
    const float rstd = rsqrtf(var + 1e-3f);

    const float4 gaA = *(const float4*)(gamma + ch), gaB = *(const float4*)(gamma + ch + 4);
    const float4 btA = *(const float4*)(beta  + ch), btB = *(const float4*)(beta  + ch + 4);
    float4 o1, o2;
    o1.x = fmaf((v[0]-mu)*rstd, gaA.x, btA.x); o1.y = fmaf((v[1]-mu)*rstd, gaA.y, btA.y);
    o1.z = fmaf((v[2]-mu)*rstd, gaA.z, btA.z); o1.w = fmaf((v[3]-mu)*rstd, gaA.w, btA.w);
    o2.x = fmaf((v[4]-mu)*rstd, gaB.x, btB.x); o2.y = fmaf((v[5]-mu)*rstd, gaB.y, btB.y);
    o2.z = fmaf((v[6]-mu)*rstd, gaB.z, btB.z); o2.w = fmaf((v[7]-mu)*rstd, gaB.w, btB.w);
    *(float4*)(out + (size_t)row*HC + ch)     = o1;
    *(float4*)(out + (size_t)row*HC + ch + 4) = o2;
}

extern "C" void kernel_launch(void* const* d_in, const int* in_sizes, int n_in,
                              void* d_out, int out_size)
{
    (void)in_sizes; (void)n_in; (void)out_size;
    const float* X      = (const float*)d_in[0];
    const float* A      = (const float*)d_in[1];
    // d_in[2..4] (E, W_edge, b_edge) are dead: sigmoid>0 always => A*gate==0 <=> A==0.
    const float* W_gat  = (const float*)d_in[5];
    const float* a_src  = (const float*)d_in[6];
    const float* a_dst  = (const float*)d_in[7];
    const float* b_gat  = (const float*)d_in[8];
    const float* gamma  = (const float*)d_in[9];
    const float* beta   = (const float*)d_in[10];
    float* out = (float*)d_out;

    cudaFuncSetAttribute(precompute_kernel, cudaFuncAttributeMaxDynamicSharedMemorySize, SMP_TOT);
    cudaFuncSetAttribute(gat_mma_kernel, cudaFuncAttributeMaxDynamicSharedMemorySize, SMB_TOT);

    precompute_kernel<<<(Bb*Nn)/16, 512, SMP_TOT>>>(X, W_gat, a_src, a_dst);
    gat_mma_kernel<<<NCTA, 1024, SMB_TOT>>>(A);
    merge_kernel<<<(Bb*Nn)/8, 256>>>(b_gat, gamma, beta, out);
}

// round 10
// speedup vs baseline: 10.6246x; 1.1880x over previous
#include <cuda_runtime.h>
#include <cstdint>

#define Bb 2
#define Nn 2048
#define Ff 128
#define Hh 4
#define HC 256
#define MI 128
#define SPLIT 4
#define JR (Nn/SPLIT)
#define NT (JR/64)
#define NCTA ((Bb*Nn/MI)*SPLIT)  // 128

// kernel-B smem: double-buffered {B-image 34816, A 34816, eb 2048}
#define KB_B(st) ((st)*71680)
#define KB_A(st) (34816 + (st)*71680)
#define KB_E(st) (69632 + (st)*71680)
#define KB_TOT   143360

// precompute smem (32 nodes/CTA)
#define SMP_XS     0
#define SMP_WS(st) (16384 + (st)*32768)
#define SMP_RS     81920
#define SMP_RD     82432
#define SMP_TOT    82944
#define SMP_TR     16384          // [32][260] overlay

__device__ unsigned g_hB [Bb*32*8704];        // f16x2 fragment image per 64-j tile
__device__ float2   g_sE [Bb*Nn*Hh];
__device__ float2   g_dE [Bb*Nn*Hh];
__device__ float    g_part[(size_t)NCTA*MI*HC];
__device__ float    g_lsum[NCTA*MI*Hh];

#define ONES_H2 0x3C003C00u

__device__ __forceinline__ unsigned pack_h2(float lo, float hi) {
    unsigned r; asm("cvt.rn.f16x2.f32 %0, %1, %2;" : "=r"(r) : "f"(hi), "f"(lo));
    return r;
}
__device__ __forceinline__ void mma_f16(float* d, unsigned a0, unsigned a1,
                                        unsigned a2, unsigned a3, unsigned b0, unsigned b1) {
    asm volatile("mma.sync.aligned.m16n8k16.row.col.f32.f16.f16.f32 "
        "{%0,%1,%2,%3}, {%4,%5,%6,%7}, {%8,%9}, {%0,%1,%2,%3};"
        : "+f"(d[0]), "+f"(d[1]), "+f"(d[2]), "+f"(d[3])
        : "r"(a0), "r"(a1), "r"(a2), "r"(a3), "r"(b0), "r"(b1));
}
__device__ __forceinline__ float pmax2(float2 a, float2 b) {
    unsigned long long av, bv, dv; float lo, hi;
    asm("mov.b64 %0, {%1, %2};" : "=l"(av) : "f"(a.x), "f"(a.y));
    asm("mov.b64 %0, {%1, %2};" : "=l"(bv) : "f"(b.x), "f"(b.y));
    asm("mul.rn.f32x2 %0, %1, %2;" : "=l"(dv) : "l"(av), "l"(bv));
    asm("mov.b64 {%0, %1}, %2;" : "=f"(lo), "=f"(hi) : "l"(dv));
    return fmaxf(lo, hi);
}
__device__ __forceinline__ uint32_t smem_u32(const void* p) {
    uint32_t a;
    asm("{ .reg .u64 t; cvta.to.shared.u64 t, %1; cvt.u32.u64 %0, t; }" : "=r"(a) : "l"(p));
    return a;
}
__device__ __forceinline__ void cp16(uint32_t dst, const void* src) {
    asm volatile("cp.async.cg.shared.global [%0], [%1], 16;" :: "r"(dst), "l"(src));
}
#define CP_COMMIT() asm volatile("cp.async.commit_group;" ::: "memory")
#define CP_WAIT(n)  asm volatile("cp.async.wait_group %0;" :: "n"(n) : "memory")

// ---------------- Kernel A ----------------
__global__ __launch_bounds__(512) void precompute_kernel(
    const float* __restrict__ X, const float* __restrict__ Wg,
    const float* __restrict__ asrc, const float* __restrict__ adst)
{
    extern __shared__ char smp[];
    float* xs    = (float*)(smp + SMP_XS);
    float* red_s = (float*)(smp + SMP_RS);
    float* red_d = (float*)(smp + SMP_RD);
    const int t   = threadIdx.x;
    const int bn0 = blockIdx.x * 32;
    const int c4  = t & 63, nq = t >> 6;
    const uint32_t smb = smem_u32(smp);

#pragma unroll
    for (int r = 0; r < 2; ++r) {
        const int u = t + r*512, n = u >> 5, f4 = u & 31;
        *(float4*)&xs[n*Ff + f4*4] = *(const float4*)(X + (size_t)(bn0+n)*Ff + f4*4);
    }
    auto stageW = [&](int fc, int st) {
#pragma unroll
        for (int k = 0; k < 4; ++k) {
            const int u = t + k*512, lf = u >> 6, cq = u & 63;
            cp16(smb + SMP_WS(st) + (lf*256 + cq*4)*4,
                 Wg + (size_t)(cq>>4)*(Ff*64) + (size_t)(fc+lf)*64 + (cq&15)*4);
        }
        CP_COMMIT();
    };

    float acc[4][4];
#pragma unroll
    for (int jj = 0; jj < 4; ++jj)
#pragma unroll
        for (int cc = 0; cc < 4; ++cc) acc[jj][cc] = 0.f;

    stageW(0, 0);
    for (int ch = 0; ch < 4; ++ch) {
        const int st = ch & 1;
        if (ch + 1 < 4) { stageW(32*(ch+1), st ^ 1); CP_WAIT(1); }
        else            { CP_WAIT(0); }
        __syncthreads();
        const float* ws = (const float*)(smp + SMP_WS(st));
#pragma unroll
        for (int lf = 0; lf < 32; ++lf) {
            const float4 w4 = *(const float4*)&ws[lf*256 + 4*c4];
            const float x0 = xs[(4*nq+0)*Ff + 32*ch + lf];
            const float x1 = xs[(4*nq+1)*Ff + 32*ch + lf];
            const float x2 = xs[(4*nq+2)*Ff + 32*ch + lf];
            const float x3 = xs[(4*nq+3)*Ff + 32*ch + lf];
            acc[0][0]=fmaf(x0,w4.x,acc[0][0]); acc[0][1]=fmaf(x0,w4.y,acc[0][1]);
            acc[0][2]=fmaf(x0,w4.z,acc[0][2]); acc[0][3]=fmaf(x0,w4.w,acc[0][3]);
            acc[1][0]=fmaf(x1,w4.x,acc[1][0]); acc[1][1]=fmaf(x1,w4.y,acc[1][1]);
            acc[1][2]=fmaf(x1,w4.z,acc[1][2]); acc[1][3]=fmaf(x1,w4.w,acc[1][3]);
            acc[2][0]=fmaf(x2,w4.x,acc[2][0]); acc[2][1]=fmaf(x2,w4.y,acc[2][1]);
            acc[2][2]=fmaf(x2,w4.z,acc[2][2]); acc[2][3]=fmaf(x2,w4.w,acc[2][3]);
            acc[3][0]=fmaf(x3,w4.x,acc[3][0]); acc[3][1]=fmaf(x3,w4.y,acc[3][1]);
            acc[3][2]=fmaf(x3,w4.z,acc[3][2]); acc[3][3]=fmaf(x3,w4.w,acc[3][3]);
        }
        __syncthreads();
    }

    const float4 as4 = *(const float4*)(asrc + 4*c4);
    const float4 ad4 = *(const float4*)(adst + 4*c4);
#pragma unroll
    for (int jj = 0; jj < 4; ++jj) {
        float ps = acc[jj][0]*as4.x + acc[jj][1]*as4.y + acc[jj][2]*as4.z + acc[jj][3]*as4.w;
        float pd = acc[jj][0]*ad4.x + acc[jj][1]*ad4.y + acc[jj][2]*ad4.z + acc[jj][3]*ad4.w;
#pragma unroll
        for (int o = 1; o < 16; o <<= 1) {
            ps += __shfl_xor_sync(0xffffffffu, ps, o);
            pd += __shfl_xor_sync(0xffffffffu, pd, o);
        }
        if ((t & 15) == 0) {
            red_s[(4*nq+jj)*4 + (c4>>4)] = ps;
            red_d[(4*nq+jj)*4 + (c4>>4)] = pd;
        }
    }
    __syncthreads();

    float* tr = (float*)(smp + SMP_TR);
#pragma unroll
    for (int jj = 0; jj < 4; ++jj)
        *(float4*)&tr[(4*nq+jj)*260 + 4*c4] =
            make_float4(acc[jj][0], acc[jj][1], acc[jj][2], acc[jj][3]);
    if (t < 128) {
        const int n = t >> 2, h = t & 3;
        const float ss = red_s[n*4 + h], sd = red_d[n*4 + h];
        g_sE[(size_t)(bn0+n)*Hh + h] = make_float2(__expf(ss), __expf(0.2f*ss));
        g_dE[(size_t)(bn0+n)*Hh + h] = make_float2(__expf(sd), __expf(0.2f*sd));
    }
    __syncthreads();

    // emit f16x2 fragment image: [(h*4+s)*544 + q*136 + c*2 + half]
    const int b = bn0 >> 11, nl = bn0 & (Nn-1);
    const int T = nl >> 6, sb = (nl & 63) >> 4;       // sb = 0 or 2
    unsigned* dst = g_hB + (size_t)(b*32 + T)*8704;
#pragma unroll
    for (int k = 0; k < 8; ++k) {
        const int u = t + k*512;                      // 0..4095
        const int half = u & 1, c = (u >> 1) & 63;
        const int q = (u >> 7) & 3, h = (u >> 9) & 3, s_rel = u >> 11;
        const int n0 = 16*s_rel + 2*q + 8*half;
        const float v0 = tr[n0*260 + h*64 + c];
        const float v1 = tr[(n0+1)*260 + h*64 + c];
        dst[(h*4 + sb + s_rel)*544 + q*136 + c*2 + half] = pack_h2(v0, v1);
    }
}

// ---------------- Kernel B: f16 m16n8k16 ----------------
__global__ __launch_bounds__(1024, 1) void gat_mma_kernel(const float* __restrict__ A)
{
    extern __shared__ char sm[];
    const uint32_t smb = smem_u32(sm);
    const int t = threadIdx.x;
    const int w = t >> 5, lane = t & 31;
    const int h = w & 3, o8 = w >> 2;
    const int rL = lane >> 2, q = lane & 3;
    const int iA = o8*16 + rL;

    const int cta = blockIdx.x;
    const int split = cta & 3, ib = cta >> 2;
    const int b = ib >> 4, i0 = (ib & 15) * MI;
    const int jbase = split * JR;

    float2 ea[2];
#pragma unroll
    for (int rh = 0; rh < 2; ++rh)
        ea[rh] = g_sE[((size_t)b*Nn + i0 + iA + 8*rh)*Hh + h];

    float acc[8][4], accl[4];
#pragma unroll
    for (int n = 0; n < 8; ++n)
#pragma unroll
        for (int u = 0; u < 4; ++u) acc[n][u] = 0.f;
#pragma unroll
    for (int u = 0; u < 4; ++u) accl[u] = 0.f;

    auto stage = [&](int tt, int st) {
        const int j0 = jbase + tt*64;
        const char* srcB = (const char*)(g_hB + (size_t)(b*32 + split*8 + tt)*8704);
#pragma unroll
        for (int k = 0; k < 2; ++k)
            cp16(smb + KB_B(st) + (t + k*1024)*16, srcB + (size_t)(t + k*1024)*16);
        if (t < 128)
            cp16(smb + KB_B(st) + (t + 2048)*16, srcB + (size_t)(t + 2048)*16);
        else if (t < 256)
            cp16(smb + KB_E(st) + (t - 128)*16,
                 (const char*)(g_dE + ((size_t)b*Nn + j0)*Hh) + (t - 128)*16);
#pragma unroll
        for (int k = 0; k < 2; ++k) {
            const int u = t + k*1024, i = u >> 4, jj = u & 15;
            cp16(smb + KB_A(st) + i*272 + jj*16,
                 (const char*)(A + ((size_t)b*Nn + i0 + i)*Nn + j0) + jj*16);
        }
        CP_COMMIT();
    };

    stage(0, 0);
    for (int tt = 0; tt < NT; ++tt) {
        const int st = tt & 1;
        if (tt + 1 < NT) { stage(tt + 1, st ^ 1); CP_WAIT(1); }
        else             { CP_WAIT(0); }
        __syncthreads();

        const unsigned* sB = (const unsigned*)(sm + KB_B(st));
        const float*   sAf = (const float*)(sm + KB_A(st));
        const float2*  sE  = (const float2*)(sm + KB_E(st));

#pragma unroll
        for (int s = 0; s < 4; ++s) {
            const int jb = 16*s + 2*q;
            const float2 e0 = sE[jb*4 + h],     e1 = sE[(jb+1)*4 + h];
            const float2 e8 = sE[(jb+8)*4 + h], e9 = sE[(jb+9)*4 + h];
            const float2 aL = *(const float2*)&sAf[iA*68 + jb];
            const float2 aH = *(const float2*)&sAf[iA*68 + jb + 8];
            const float2 bL = *(const float2*)&sAf[(iA+8)*68 + jb];
            const float2 bH = *(const float2*)&sAf[(iA+8)*68 + jb + 8];

            const float p00 = (aL.x!=0.f) ? pmax2(ea[0], e0) : 0.f;
            const float p01 = (aL.y!=0.f) ? pmax2(ea[0], e1) : 0.f;
            const float p08 = (aH.x!=0.f) ? pmax2(ea[0], e8) : 0.f;
            const float p09 = (aH.y!=0.f) ? pmax2(ea[0], e9) : 0.f;
            const float p10 = (bL.x!=0.f) ? pmax2(ea[1], e0) : 0.f;
            const float p11 = (bL.y!=0.f) ? pmax2(ea[1], e1) : 0.f;
            const float p18 = (bH.x!=0.f) ? pmax2(ea[1], e8) : 0.f;
            const float p19 = (bH.y!=0.f) ? pmax2(ea[1], e9) : 0.f;
            const unsigned f0 = pack_h2(p00, p01);
            const unsigned f1 = pack_h2(p10, p11);
            const unsigned f2 = pack_h2(p08, p09);
            const unsigned f3 = pack_h2(p18, p19);

            const uint2* bp = (const uint2*)sB + ((h*4 + s)*544 + q*136)/2;
#pragma unroll
            for (int n = 0; n < 8; ++n) {
                const uint2 bv = bp[8*n + rL];
                mma_f16(acc[n], f0, f1, f2, f3, bv.x, bv.y);
            }
            mma_f16(accl, f0, f1, f2, f3, ONES_H2, ONES_H2);
        }
        __syncthreads();
    }

    if (q == 0) {
        g_lsum[((size_t)cta*MI + iA)*Hh + h]     = accl[0];
        g_lsum[((size_t)cta*MI + iA + 8)*Hh + h] = accl[2];
    }
    float* gp = g_part + (size_t)cta*MI*HC;
#pragma unroll
    for (int n = 0; n < 8; ++n) {
        const int ch = h*64 + 8*n + 2*q;
        *(float2*)(gp + (size_t)iA*HC + ch)     = make_float2(acc[n][0], acc[n][1]);
        *(float2*)(gp + (size_t)(iA+8)*HC + ch) = make_float2(acc[n][2], acc[n][3]);
    }
}

// ---------------- Kernel C ----------------
__global__ __launch_bounds__(256) void merge_kernel(
    const float* __restrict__ bgat, const float* __restrict__ gamma,
    const float* __restrict__ beta, float* __restrict__ out)
{
    const int t = threadIdx.x, w = t >> 5, lane = t & 31;
    const int row = blockIdx.x*8 + w;
    const int ib = row >> 7, il = row & 127, hd = lane >> 3;

    float4 n0 = {0,0,0,0}, n1 = {0,0,0,0};
    float ls = 0.f;
#pragma unroll
    for (int s = 0; s < SPLIT; ++s) {
        const int cta = ib*SPLIT + s;
        const float4* p = (const float4*)(g_part + ((size_t)cta*MI + il)*HC + lane*8);
        const float4 x = p[0], y = p[1];
        n0.x += x.x; n0.y += x.y; n0.z += x.z; n0.w += x.w;
        n1.x += y.x; n1.y += y.y; n1.z += y.z; n1.w += y.w;
        ls += g_lsum[((size_t)cta*MI + il)*Hh + hd];
    }
    const float inv = __fdividef(1.f, ls);
    const int ch = lane*8;
    const float4 bgA = *(const float4*)(bgat + ch), bgB = *(const float4*)(bgat + ch + 4);
    float v[8];
    v[0]=fmaf(n0.x,inv,bgA.x); v[1]=fmaf(n0.y,inv,bgA.y);
    v[2]=fmaf(n0.z,inv,bgA.z); v[3]=fmaf(n0.w,inv,bgA.w);
    v[4]=fmaf(n1.x,inv,bgB.x); v[5]=fmaf(n1.y,inv,bgB.y);
    v[6]=fmaf(n1.z,inv,bgB.z); v[7]=fmaf(n1.w,inv,bgB.w);
    float s1 = 0.f, s2 = 0.f;
#pragma unroll
    for (int k = 0; k < 8; ++k) {
        float x = v[k];
        x = x > 0.f ? x : expm1f(x);
        v[k] = x; s1 += x; s2 = fmaf(x, x, s2);
    }
#pragma unroll
    for (int o = 16; o; o >>= 1) {
        s1 += __shfl_xor_sync(0xffffffffu, s1, o);
        s2 += __shfl_xor_sync(0xffffffffu, s2, o);
    }
    const float mu = s1 * (1.f/HC);
    const float var = fmaf(-mu, mu, s2 * (1.f/HC));
    const float rstd = rsqrtf(var + 1e-3f);
    const float4 gaA = *(const float4*)(gamma + ch), gaB = *(const float4*)(gamma + ch + 4);
    const float4 btA = *(const float4*)(beta + ch),  btB = *(const float4*)(beta + ch + 4);
    float4 o1, o2;
    o1.x=fmaf((v[0]-mu)*rstd,gaA.x,btA.x); o1.y=fmaf((v[1]-mu)*rstd,gaA.y,btA.y);
    o1.z=fmaf((v[2]-mu)*rstd,gaA.z,btA.z); o1.w=fmaf((v[3]-mu)*rstd,gaA.w,btA.w);
    o2.x=fmaf((v[4]-mu)*rstd,gaB.x,btB.x); o2.y=fmaf((v[5]-mu)*rstd,gaB.y,btB.y);
    o2.z=fmaf((v[6]-mu)*rstd,gaB.z,btB.z); o2.w=fmaf((v[7]-mu)*rstd,gaB.w,btB.w);
    *(float4*)(out + (size_t)row*HC + ch)     = o1;
    *(float4*)(out + (size_t)row*HC + ch + 4) = o2;
}

extern "C" void kernel_launch(void* const* d_in, const int* in_sizes, int n_in,
                              void* d_out, int out_size)
{
    (void)in_sizes; (void)n_in; (void)out_size;
    const float* X     = (const float*)d_in[0];
    const float* A     = (const float*)d_in[1];
    // E/W_edge/b_edge dead: sigmoid>0 => A*gate==0 <=> A==0
    const float* W_gat = (const float*)d_in[5];
    const float* a_src = (const float*)d_in[6];
    const float* a_dst = (const float*)d_in[7];
    const float* b_gat = (const float*)d_in[8];
    const float* gamma = (const float*)d_in[9];
    const float* beta  = (const float*)d_in[10];
    float* out = (float*)d_out;

    cudaFuncSetAttribute(precompute_kernel, cudaFuncAttributeMaxDynamicSharedMemorySize, SMP_TOT);
    cudaFuncSetAttribute(gat_mma_kernel, cudaFuncAttributeMaxDynamicSharedMemorySize, KB_TOT);

    precompute_kernel<<<(Bb*Nn)/32, 512, SMP_TOT>>>(X, W_gat, a_src, a_dst);
    gat_mma_kernel<<<NCTA, 1024, KB_TOT>>>(A);
    merge_kernel<<<(Bb*Nn)/8, 256>>>(b_gat, gamma, beta, out);
}